// round 6
// baseline (speedup 1.0000x reference)
#include <cuda_runtime.h>
#include <cuda_fp16.h>
#include <math.h>
#include <stdint.h>

// Problem constants
#define BB   4
#define SS   4096
#define DD   1024
#define HH   8
#define DK_  128
#define SEG_ 512
#define NSEG 8
#define DH_  4096
#define MROWS (BB*SS)   // 16384
#define QS   3072       // fused qkv row stride

// ---------------- scratch ----------------
__device__ float g_qkv[(size_t)MROWS*QS];
__device__ float g_x1[(size_t)MROWS*DD];
__device__ float g_ff[(size_t)MROWS*DH_];      // reused as 2 half buffers for FFN1 split out
__device__ float g_ms[(size_t)NSEG*BB*HH*DK_*DK_];
__device__ float g_mp[(size_t)NSEG*BB*HH*DK_*DK_];
__device__ float g_zs[(size_t)NSEG*BB*HH*DK_];
__device__ float g_zp[(size_t)NSEG*BB*HH*DK_];
// fp16 split activation buffers [M][1024]
__device__ __half g_ah[(size_t)MROWS*DD];
__device__ __half g_al[(size_t)MROWS*DD];
// transposed fp16 weights [N][K]
__device__ __half g_bqkv[(size_t)QS*DD];
__device__ __half g_bo[(size_t)DD*DD];
__device__ __half g_bw1[(size_t)DH_*DD];
__device__ __half g_bw2[(size_t)DD*DH_];

__device__ __forceinline__ float gelu_f(float x) {
    float x3 = x*x*x;
    float t = tanhf(0.7978845608028654f*(x + 0.044715f*x3));
    return 0.5f*x*(1.f + t);
}

// ================= PTX helpers =================
__device__ __forceinline__ uint32_t smem_u32(const void* p) {
    uint32_t a;
    asm("{ .reg .u64 t; cvta.to.shared.u64 t, %1; cvt.u32.u64 %0, t; }" : "=r"(a) : "l"(p));
    return a;
}
__device__ __forceinline__ void cpa16(uint32_t d, const void* s) {
    asm volatile("cp.async.cg.shared.global [%0], [%1], 16;"
                 :: "r"(d), "l"(__cvta_generic_to_global((void*)s)) : "memory");
}
#define SWZ(x) ((x) ^ (((x) >> 3) & 0x70))

#define LDSM4(r0,r1,r2,r3,addr) \
    asm volatile("ldmatrix.sync.aligned.m8n8.x4.shared.b16 {%0,%1,%2,%3}, [%4];" \
                 : "=r"(r0),"=r"(r1),"=r"(r2),"=r"(r3) : "r"(addr))

#define MMA16816(d, a, b) \
    asm volatile("mma.sync.aligned.m16n8k16.row.col.f32.f16.f16.f32 " \
                 "{%0,%1,%2,%3}, {%4,%5,%6,%7}, {%8,%9}, {%0,%1,%2,%3};" \
                 : "+f"((d)[0]),"+f"((d)[1]),"+f"((d)[2]),"+f"((d)[3]) \
                 : "r"((a)[0]),"r"((a)[1]),"r"((a)[2]),"r"((a)[3]), \
                   "r"((b)[0]),"r"((b)[1]))

// ---------------- LayerNorm -> fp16 hi/lo split ----------------
__global__ void ln_kernel(const float* __restrict__ x, const float* __restrict__ gamma,
                          const float* __restrict__ beta,
                          __half* __restrict__ Ah, __half* __restrict__ Al) {
    __shared__ float s1[256], s2[256];
    const int row = blockIdx.x;
    const int tid = threadIdx.x;
    const float* xr = x + (size_t)row*DD;
    float4 v = *(const float4*)&xr[tid*4];
    float s  = v.x+v.y+v.z+v.w;
    float ss = v.x*v.x+v.y*v.y+v.z*v.z+v.w*v.w;
    s1[tid]=s; s2[tid]=ss; __syncthreads();
    for (int o=128;o>0;o>>=1){ if(tid<o){s1[tid]+=s1[tid+o]; s2[tid]+=s2[tid+o];} __syncthreads(); }
    float mu  = s1[0]*(1.f/DD);
    float var = s2[0]*(1.f/DD) - mu*mu;
    float inv = rsqrtf(var + 1e-5f);
    float4 g  = *(const float4*)&gamma[tid*4];
    float4 bt = *(const float4*)&beta[tid*4];
    float o0 = (v.x-mu)*inv*g.x + bt.x;
    float o1 = (v.y-mu)*inv*g.y + bt.y;
    float o2 = (v.z-mu)*inv*g.z + bt.z;
    float o3 = (v.w-mu)*inv*g.w + bt.w;
    __half h0=__float2half_rn(o0), h1=__float2half_rn(o1), h2=__float2half_rn(o2), h3=__float2half_rn(o3);
    size_t base = (size_t)row*DD + tid*4;
    *(__half2*)&Ah[base]   = __halves2half2(h0, h1);
    *(__half2*)&Ah[base+2] = __halves2half2(h2, h3);
    *(__half2*)&Al[base]   = __halves2half2(__float2half_rn(o0-__half2float(h0)),
                                            __float2half_rn(o1-__half2float(h1)));
    *(__half2*)&Al[base+2] = __halves2half2(__float2half_rn(o2-__half2float(h2)),
                                            __float2half_rn(o3-__half2float(h3)));
}

// ---------------- Weight prep: W[K,N] -> Bp[N][K] fp16 (transposed) ----------------
__global__ void prep_w_kernel(const float* __restrict__ W, __half* __restrict__ Bp,
                              int K, int N) {
    __shared__ float ts[32][33];
    const int n0 = blockIdx.x*32, k0 = blockIdx.y*32;
    const int tx = threadIdx.x, ty = threadIdx.y;   // (32,8)
    #pragma unroll
    for (int i = 0; i < 4; i++)
        ts[ty+8*i][tx] = W[(size_t)(k0+ty+8*i)*N + n0+tx];
    __syncthreads();
    #pragma unroll
    for (int i = 0; i < 4; i++) {
        int nl = ty + 8*i;
        Bp[(size_t)(n0+nl)*K + k0+tx] = __float2half_rn(ts[tx][nl]);
    }
}

// ---------------- mma.sync fp16 GEMM ----------------
// BM=256, BN=128, BK=64. Per stage loads {Ah, Al, B}; 2 MMAs per B fragment
// (hi then lo into the same fp32 acc). Double-buffered (160KB smem, 1 CTA/SM).
#define GBK 64
#define A_ST 32768                       // 256 rows * 128B
#define B_ST 16384                       // 128 rows * 128B
#define STAGE_BYTES (2*A_ST + B_ST)      // 81920
#define HG_SMEM (2*STAGE_BYTES)          // 163840

__global__ __launch_bounds__(256, 1) void hgemm_kernel(
    const __half* __restrict__ Ah, const __half* __restrict__ Al,
    const __half* __restrict__ Bp,
    const float* __restrict__ bias, const float* __restrict__ add,
    float* __restrict__ C, __half* __restrict__ Cah, __half* __restrict__ Cal,
    int M, int N, int K, int act, int splitOut)
{
    extern __shared__ char dsm[];
    const uint32_t sb = smem_u32(dsm);
    const int tid = threadIdx.x;
    const int lane = tid & 31, wid = tid >> 5;
    const int row0 = blockIdx.y * 256, col0 = blockIdx.x * 128;
    const int NT = K / GBK;

    const int wm = (wid >> 1) * 64;     // 4 m-groups
    const int wn = (wid & 1) * 64;      // 2 n-groups

    float acc[4][8][4];
    #pragma unroll
    for (int i=0;i<4;i++)
        #pragma unroll
        for (int j=0;j<8;j++)
            #pragma unroll
            for (int c=0;c<4;c++) acc[i][j][c]=0.f;

    auto load_tile = [&](int t, int s) {
        int k0 = t * GBK;
        uint32_t stAh = sb + s*STAGE_BYTES;
        uint32_t stAl = stAh + A_ST;
        uint32_t stB  = stAh + 2*A_ST;
        #pragma unroll
        for (int i = 0; i < 8; i++) {
            int ch = i*256 + tid;           // 0..2047: 256 rows x 8 chunks
            int r = ch >> 3, c = (ch & 7) * 8;
            size_t go = (size_t)(row0 + r)*K + k0 + c;
            cpa16(stAh + SWZ(ch*16), Ah + go);
            cpa16(stAl + SWZ(ch*16), Al + go);
        }
        #pragma unroll
        for (int i = 0; i < 4; i++) {
            int ch = i*256 + tid;           // 0..1023: 128 rows x 8 chunks
            int r = ch >> 3, c = (ch & 7) * 8;
            cpa16(stB + SWZ(ch*16), Bp + (size_t)(col0 + r)*K + k0 + c);
        }
        asm volatile("cp.async.commit_group;" ::: "memory");
    };

    load_tile(0, 0);

    const int aRow = wm + (lane & 15);
    const int aColB = ((lane >> 4) & 1) * 16;
    const int bRow = wn + (lane & 7) + ((lane >> 4) & 1) * 8;
    const int bColB = ((lane >> 3) & 1) * 16;

    for (int t = 0; t < NT; t++) {
        if (t + 1 < NT) {
            load_tile(t + 1, (t + 1) & 1);
            asm volatile("cp.async.wait_group 1;" ::: "memory");
        } else {
            asm volatile("cp.async.wait_group 0;" ::: "memory");
        }
        __syncthreads();
        uint32_t stAh = sb + (t & 1)*STAGE_BYTES;
        uint32_t stAl = stAh + A_ST;
        uint32_t stB  = stAh + 2*A_ST;
        #pragma unroll
        for (int kk = 0; kk < 4; kk++) {
            uint32_t bf[8][2];
            #pragma unroll
            for (int nt2 = 0; nt2 < 4; nt2++) {
                uint32_t r0,r1,r2,r3;
                uint32_t addr = stB + SWZ((uint32_t)(bRow + nt2*16)*128 + kk*32 + bColB);
                LDSM4(r0, r1, r2, r3, addr);
                bf[nt2*2][0]=r0; bf[nt2*2][1]=r1; bf[nt2*2+1][0]=r2; bf[nt2*2+1][1]=r3;
            }
            uint32_t af[4][4];
            // hi pass
            #pragma unroll
            for (int mt = 0; mt < 4; mt++) {
                uint32_t addr = stAh + SWZ((uint32_t)(aRow + mt*16)*128 + kk*32 + aColB);
                LDSM4(af[mt][0], af[mt][1], af[mt][2], af[mt][3], addr);
            }
            #pragma unroll
            for (int mt = 0; mt < 4; mt++)
                #pragma unroll
                for (int nt = 0; nt < 8; nt++)
                    MMA16816(acc[mt][nt], af[mt], bf[nt]);
            // lo pass (reuse fragment regs)
            #pragma unroll
            for (int mt = 0; mt < 4; mt++) {
                uint32_t addr = stAl + SWZ((uint32_t)(aRow + mt*16)*128 + kk*32 + aColB);
                LDSM4(af[mt][0], af[mt][1], af[mt][2], af[mt][3], addr);
            }
            #pragma unroll
            for (int mt = 0; mt < 4; mt++)
                #pragma unroll
                for (int nt = 0; nt < 8; nt++)
                    MMA16816(acc[mt][nt], af[mt], bf[nt]);
        }
        __syncthreads();
    }

    const int erow = lane >> 2, ecol = (lane & 3) * 2;
    #pragma unroll
    for (int mt = 0; mt < 4; mt++) {
        #pragma unroll
        for (int half_ = 0; half_ < 2; half_++) {
            int row = row0 + wm + mt*16 + erow + half_*8;
            size_t rbase = (size_t)row * N;
            #pragma unroll
            for (int nt = 0; nt < 8; nt++) {
                int col = col0 + wn + nt*8 + ecol;
                float v0 = acc[mt][nt][half_*2+0];
                float v1 = acc[mt][nt][half_*2+1];
                if (bias) { v0 += bias[col]; v1 += bias[col+1]; }
                if (act)  { v0 = gelu_f(v0); v1 = gelu_f(v1); }
                if (add)  {
                    const float2 a2 = *(const float2*)&add[rbase + col];
                    v0 += a2.x; v1 += a2.y;
                }
                if (splitOut) {
                    __half h0 = __float2half_rn(v0), h1 = __float2half_rn(v1);
                    *(__half2*)&Cah[rbase + col] = __halves2half2(h0, h1);
                    *(__half2*)&Cal[rbase + col] =
                        __halves2half2(__float2half_rn(v0 - __half2float(h0)),
                                       __float2half_rn(v1 - __half2float(h1)));
                } else {
                    *(float2*)&C[rbase + col] = make_float2(v0, v1);
                }
            }
        }
    }
}

// ---------------- Per-segment memory contributions (stride QS) ----------------
__global__ void segkv_kernel(const float* __restrict__ k, const float* __restrict__ v,
                             float* __restrict__ ms, float* __restrict__ zs)
{
    __shared__ float sks[32][128];
    __shared__ float svs[32][128];
    __shared__ float zacc[128];
    const int seg = blockIdx.x, bh = blockIdx.y;
    const int b = bh >> 3, h = bh & 7;
    const int tid = threadIdx.x;
    const int ty = tid >> 4, tx = tid & 15;
    float acc[8][8];
    #pragma unroll
    for (int i=0;i<8;i++)
        #pragma unroll
        for (int j=0;j<8;j++) acc[i][j]=0.f;
    if (tid < 128) zacc[tid] = 0.f;
    size_t base = ((size_t)b*SS + seg*SEG_)*QS + h*DK_;
    for (int p0 = 0; p0 < SEG_; p0 += 32) {
        __syncthreads();
        for (int i = tid; i < 32*32; i += 256) {
            int row = i >> 5, c4 = (i & 31)*4;
            float4 kv = *(const float4*)&k[base + (size_t)(p0+row)*QS + c4];
            kv.x = kv.x>0.f?kv.x+1.f:__expf(kv.x);
            kv.y = kv.y>0.f?kv.y+1.f:__expf(kv.y);
            kv.z = kv.z>0.f?kv.z+1.f:__expf(kv.z);
            kv.w = kv.w>0.f?kv.w+1.f:__expf(kv.w);
            *(float4*)&sks[row][c4] = kv;
            *(float4*)&svs[row][c4] = *(const float4*)&v[base + (size_t)(p0+row)*QS + c4];
        }
        __syncthreads();
        if (tid < 128) {
            float za = 0.f;
            for (int p = 0; p < 32; p++) za += sks[p][tid];
            zacc[tid] += za;
        }
        #pragma unroll 4
        for (int p = 0; p < 32; p++) {
            float4 k0 = *(const float4*)&sks[p][ty*8];
            float4 k1 = *(const float4*)&sks[p][ty*8+4];
            float4 v0 = *(const float4*)&svs[p][tx*8];
            float4 v1 = *(const float4*)&svs[p][tx*8+4];
            float kr[8] = {k0.x,k0.y,k0.z,k0.w,k1.x,k1.y,k1.z,k1.w};
            float vr[8] = {v0.x,v0.y,v0.z,v0.w,v1.x,v1.y,v1.z,v1.w};
            #pragma unroll
            for (int i=0;i<8;i++)
                #pragma unroll
                for (int j=0;j<8;j++) acc[i][j] += kr[i]*vr[j];
        }
    }
    size_t obase = ((size_t)seg*32 + bh)*DK_*DK_;
    #pragma unroll
    for (int i=0;i<8;i++)
        #pragma unroll
        for (int j=0;j<8;j++)
            ms[obase + (size_t)(ty*8+i)*DK_ + tx*8+j] = acc[i][j];
    if (tid < 128) zs[((size_t)seg*32 + bh)*DK_ + tid] = zacc[tid];
}

// ---------------- Exclusive prefix over 8 segments ----------------
__global__ void prefix_kernel(const float* __restrict__ ms, const float* __restrict__ zs,
                              float* __restrict__ mp, float* __restrict__ zp)
{
    size_t idx = (size_t)blockIdx.x*256 + threadIdx.x;
    const size_t stride = (size_t)BB*HH*DK_*DK_;
    if (idx < stride) {
        float a = 0.f;
        #pragma unroll
        for (int t = 0; t < NSEG; t++) { mp[t*stride + idx] = a; a += ms[t*stride + idx]; }
    }
    if (idx < (size_t)BB*HH*DK_) {
        const size_t zstr = (size_t)BB*HH*DK_;
        float a = 1.f/128.f;
        #pragma unroll
        for (int t = 0; t < NSEG; t++) { zp[t*zstr + idx] = a; a += zs[t*zstr + idx]; }
    }
}

// ---------------- Attention: register-blocked, float4 smem ----------------
#define AP 132
#define SPP 68
#define ATTN_SMEM_FLOATS (64*AP*2 + 64*128 + 64*SPP + 128 + 4*64)
__global__ __launch_bounds__(256, 1) void attn_kernel(
    const float* __restrict__ q, const float* __restrict__ k,
    const float* __restrict__ v, const float* __restrict__ memp,
    const float* __restrict__ zp, const float* __restrict__ betas,
    __half* __restrict__ Oah, __half* __restrict__ Oal)
{
    extern __shared__ float sh[];
    float* Qs  = sh;                 // [64][AP]
    float* Ks  = Qs + 64*AP;         // [64][AP]  (later reused for sq)
    float* Vs  = Ks + 64*AP;         // [64][128] (later reused for M chunks)
    float* Spt = Vs + 64*128;        // [64 c][SPP]
    float* Zs  = Spt + 64*SPP;       // [128]
    float* mrow = Zs + 128;
    float* lrow = mrow + 64;
    float* arow = lrow + 64;
    float* drow = arow + 64;

    const int qt = blockIdx.x, seg = blockIdx.y;
    const int b = blockIdx.z >> 3, h = blockIdx.z & 7;
    const int tid = threadIdx.x;
    const int ty = tid >> 4, tx = tid & 15;

    const float* Z = zp + (((size_t)seg*BB + b)*HH + h)*DK_;
    size_t qbase = ((size_t)b*SS + seg*SEG_ + qt*64)*QS + h*DK_;
    #pragma unroll
    for (int i = tid; i < 64*32; i += 256) {
        int row = i >> 5, c4 = (i & 31)*4;
        *(float4*)&Qs[row*AP + c4] = *(const float4*)&q[qbase + (size_t)row*QS + c4];
    }
    if (tid < 128) Zs[tid] = Z[tid];
    if (tid < 64) { mrow[tid] = -INFINITY; lrow[tid] = 0.f; }
    float o[4][8];
    #pragma unroll
    for (int i=0;i<4;i++)
        #pragma unroll
        for (int j=0;j<8;j++) o[i][j]=0.f;
    __syncthreads();

    const float scale = 0.08838834764831845f;
    for (int kt = 0; kt <= qt; kt++) {
        size_t kbase = ((size_t)b*SS + seg*SEG_ + kt*64)*QS + h*DK_;
        #pragma unroll
        for (int i = tid; i < 64*32; i += 256) {
            int row = i >> 5, c4 = (i & 31)*4;
            *(float4*)&Ks[row*AP + c4] = *(const float4*)&k[kbase + (size_t)row*QS + c4];
            *(float4*)&Vs[row*128 + c4] = *(const float4*)&v[kbase + (size_t)row*QS + c4];
        }
        __syncthreads();

        float s[4][4];
        #pragma unroll
        for (int i=0;i<4;i++)
            #pragma unroll
            for (int j=0;j<4;j++) s[i][j]=0.f;
        #pragma unroll 4
        for (int d = 0; d < 128; d += 4) {
            float4 qv[4], kv[4];
            #pragma unroll
            for (int i=0;i<4;i++) qv[i] = *(const float4*)&Qs[(ty*4+i)*AP + d];
            #pragma unroll
            for (int j=0;j<4;j++) kv[j] = *(const float4*)&Ks[(tx*4+j)*AP + d];
            #pragma unroll
            for (int i=0;i<4;i++)
                #pragma unroll
                for (int j=0;j<4;j++)
                    s[i][j] += qv[i].x*kv[j].x + qv[i].y*kv[j].y
                             + qv[i].z*kv[j].z + qv[i].w*kv[j].w;
        }
        #pragma unroll
        for (int j=0;j<4;j++) {
            int c = tx*4 + j;
            #pragma unroll
            for (int i=0;i<4;i++) {
                int r = ty*4 + i;
                float vv = s[i][j]*scale;
                if (kt == qt && c > r) vv = -INFINITY;
                Spt[c*SPP + r] = vv;
            }
        }
        __syncthreads();

        if (tid < 64) {
            float mold = mrow[tid], mx = mold;
            for (int c = 0; c < 64; c++) mx = fmaxf(mx, Spt[c*SPP + tid]);
            float al = __expf(mold - mx);
            float ls = 0.f;
            for (int c = 0; c < 64; c++) {
                float p = __expf(Spt[c*SPP + tid] - mx);
                Spt[c*SPP + tid] = p; ls += p;
            }
            lrow[tid] = lrow[tid]*al + ls;
            mrow[tid] = mx; arow[tid] = al;
        }
        __syncthreads();

        float a_[4];
        #pragma unroll
        for (int i=0;i<4;i++) a_[i] = arow[ty*4+i];
        #pragma unroll
        for (int i=0;i<4;i++)
            #pragma unroll
            for (int j=0;j<8;j++) o[i][j] *= a_[i];
        #pragma unroll 2
        for (int c = 0; c < 64; c++) {
            float4 p4 = *(const float4*)&Spt[c*SPP + ty*4];
            float pp[4] = {p4.x, p4.y, p4.z, p4.w};
            float4 v0 = *(const float4*)&Vs[c*128 + tx*8];
            float4 v1 = *(const float4*)&Vs[c*128 + tx*8 + 4];
            float vr[8] = {v0.x,v0.y,v0.z,v0.w,v1.x,v1.y,v1.z,v1.w};
            #pragma unroll
            for (int i=0;i<4;i++)
                #pragma unroll
                for (int j=0;j<8;j++) o[i][j] += pp[i]*vr[j];
        }
        __syncthreads();
    }

    #pragma unroll
    for (int i = tid; i < 64*128; i += 256) {
        int row = i >> 7, d = i & 127;
        float qv = Qs[row*AP + d];
        Ks[row*AP + d] = qv > 0.f ? qv + 1.f : __expf(qv);
    }
    __syncthreads();
    if (tid < 64) {
        float ds = 0.f;
        #pragma unroll 4
        for (int d = 0; d < 128; d += 4) {
            float4 sq4 = *(const float4*)&Ks[tid*AP + d];
            float4 z4  = *(const float4*)&Zs[d];
            ds += sq4.x*z4.x + sq4.y*z4.y + sq4.z*z4.z + sq4.w*z4.w;
        }
        drow[tid] = ds;
    }

    const float* M = memp + (((size_t)seg*BB + b)*HH + h)*DK_*DK_;
    float am[4][8];
    #pragma unroll
    for (int i=0;i<4;i++)
        #pragma unroll
        for (int j=0;j<8;j++) am[i][j]=0.f;
    for (int d0 = 0; d0 < 128; d0 += 32) {
        __syncthreads();
        #pragma unroll
        for (int i = tid; i < 32*32; i += 256) {
            int row = i >> 5, c4 = (i & 31)*4;
            *(float4*)&Vs[row*128 + c4] = *(const float4*)&M[(size_t)(d0+row)*128 + c4];
        }
        __syncthreads();
        #pragma unroll 2
        for (int dd = 0; dd < 32; dd += 4) {
            float sqa[4][4];
            #pragma unroll
            for (int i=0;i<4;i++) {
                float4 s4 = *(const float4*)&Ks[(ty*4+i)*AP + d0 + dd];
                sqa[i][0]=s4.x; sqa[i][1]=s4.y; sqa[i][2]=s4.z; sqa[i][3]=s4.w;
            }
            #pragma unroll
            for (int t = 0; t < 4; t++) {
                float4 m0 = *(const float4*)&Vs[(dd+t)*128 + tx*8];
                float4 m1 = *(const float4*)&Vs[(dd+t)*128 + tx*8 + 4];
                float mr[8] = {m0.x,m0.y,m0.z,m0.w,m1.x,m1.y,m1.z,m1.w};
                #pragma unroll
                for (int i=0;i<4;i++)
                    #pragma unroll
                    for (int j=0;j<8;j++) am[i][j] += sqa[i][t]*mr[j];
            }
        }
    }

    float gte[8];
    #pragma unroll
    for (int j=0;j<8;j++)
        gte[j] = 1.f / (1.f + __expf(-betas[h*DK_ + tx*8 + j]));
    #pragma unroll
    for (int i=0;i<4;i++) {
        int r = ty*4 + i;
        float dinv = 1.f / drow[r];
        float linv = 1.f / lrow[r];
        size_t ob = ((size_t)b*SS + seg*SEG_ + qt*64 + r)*DD + h*DK_ + tx*8;
        #pragma unroll
        for (int j=0;j<8;j+=2) {
            float u0 = gte[j]  *(am[i][j]  *dinv) + (1.f-gte[j])  *(o[i][j]  *linv);
            float u1 = gte[j+1]*(am[i][j+1]*dinv) + (1.f-gte[j+1])*(o[i][j+1]*linv);
            __half h0 = __float2half_rn(u0), h1 = __float2half_rn(u1);
            *(__half2*)&Oah[ob + j] = __halves2half2(h0, h1);
            *(__half2*)&Oal[ob + j] = __halves2half2(__float2half_rn(u0-__half2float(h0)),
                                                     __float2half_rn(u1-__half2float(h1)));
        }
    }
}

// ---------------- launch ----------------
extern "C" void kernel_launch(void* const* d_in, const int* in_sizes, int n_in,
                              void* d_out, int out_size)
{
    const float* x     = (const float*)d_in[0];
    const float* ln_g  = (const float*)d_in[1];
    const float* ln_b  = (const float*)d_in[2];
    const float* Wq    = (const float*)d_in[3];
    const float* Wk    = (const float*)d_in[4];
    const float* Wv    = (const float*)d_in[5];
    const float* Wo    = (const float*)d_in[6];
    const float* betas = (const float*)d_in[7];
    const float* w1    = (const float*)d_in[8];
    const float* b1    = (const float*)d_in[9];
    const float* w2    = (const float*)d_in[10];
    const float* b2    = (const float*)d_in[11];
    float* out = (float*)d_out;

    float *qkv, *x1, *ff, *ms, *mp, *zs, *zp;
    __half *ah, *al, *bqkv, *bo, *bw1, *bw2;
    cudaGetSymbolAddress((void**)&qkv, g_qkv);
    cudaGetSymbolAddress((void**)&x1, g_x1);
    cudaGetSymbolAddress((void**)&ff, g_ff);
    cudaGetSymbolAddress((void**)&ms, g_ms);
    cudaGetSymbolAddress((void**)&mp, g_mp);
    cudaGetSymbolAddress((void**)&zs, g_zs);
    cudaGetSymbolAddress((void**)&zp, g_zp);
    cudaGetSymbolAddress((void**)&ah, g_ah);
    cudaGetSymbolAddress((void**)&al, g_al);
    cudaGetSymbolAddress((void**)&bqkv, g_bqkv);
    cudaGetSymbolAddress((void**)&bo, g_bo);
    cudaGetSymbolAddress((void**)&bw1, g_bw1);
    cudaGetSymbolAddress((void**)&bw2, g_bw2);

    __half* ah2 = (__half*)ff;
    __half* al2 = (__half*)ff + (size_t)MROWS*DH_;

    const int attn_smem = ATTN_SMEM_FLOATS * 4;
    cudaFuncSetAttribute(attn_kernel, cudaFuncAttributeMaxDynamicSharedMemorySize, attn_smem);
    cudaFuncSetAttribute(hgemm_kernel, cudaFuncAttributeMaxDynamicSharedMemorySize, HG_SMEM);

    dim3 wblk(32, 8);

    // weight prep: fused QKV rows [0:1024)=Wq, [1024:2048)=Wk, [2048:3072)=Wv
    prep_w_kernel<<<dim3(1024/32, 1024/32), wblk>>>(Wq, bqkv,                      1024, 1024);
    prep_w_kernel<<<dim3(1024/32, 1024/32), wblk>>>(Wk, bqkv + (size_t)1024*1024,  1024, 1024);
    prep_w_kernel<<<dim3(1024/32, 1024/32), wblk>>>(Wv, bqkv + (size_t)2048*1024,  1024, 1024);
    prep_w_kernel<<<dim3(1024/32, 1024/32), wblk>>>(Wo, bo, 1024, 1024);
    prep_w_kernel<<<dim3(4096/32, 1024/32), wblk>>>(w1, bw1, 1024, 4096);
    prep_w_kernel<<<dim3(1024/32, 4096/32), wblk>>>(w2, bw2, 4096, 1024);

    // 1) LN1 -> split
    ln_kernel<<<MROWS, 256>>>(x, ln_g, ln_b, ah, al);
    // 2) fused QKV projection (N=3072)
    hgemm_kernel<<<dim3(QS/128, MROWS/256), 256, HG_SMEM>>>(ah, al, bqkv, nullptr, nullptr,
                                                            qkv, nullptr, nullptr, MROWS, QS, DD, 0, 0);
    // 3-5) infini-attention
    segkv_kernel<<<dim3(NSEG, BB*HH), 256>>>(qkv + 1024, qkv + 2048, ms, zs);
    prefix_kernel<<<(BB*HH*DK_*DK_)/256, 256>>>(ms, zs, mp, zp);
    attn_kernel<<<dim3(8, NSEG, BB*HH), 256, attn_smem>>>(qkv, qkv + 1024, qkv + 2048,
                                                          mp, zp, betas, ah, al);
    // 6) output projection + residual
    hgemm_kernel<<<dim3(DD/128, MROWS/256), 256, HG_SMEM>>>(ah, al, bo, nullptr, x, x1,
                                                            nullptr, nullptr, MROWS, DD, DD, 0, 0);
    // 7) LN2 -> split
    ln_kernel<<<MROWS, 256>>>(x1, ln_g, ln_b, ah, al);
    // 8) FFN1 + bias + gelu -> split out
    hgemm_kernel<<<dim3(DH_/128, MROWS/256), 256, HG_SMEM>>>(ah, al, bw1, b1, nullptr, nullptr,
                                                             ah2, al2, MROWS, DH_, DD, 1, 1);
    // 9) FFN2 + bias + residual -> out
    hgemm_kernel<<<dim3(DD/128, MROWS/256), 256, HG_SMEM>>>(ah2, al2, bw2, b2, x1, out,
                                                            nullptr, nullptr, MROWS, DD, DH_, 0, 0);
}

// round 8
// speedup vs baseline: 1.2715x; 1.2715x over previous
#include <cuda_runtime.h>
#include <cuda_fp16.h>
#include <math.h>
#include <stdint.h>

// Problem constants
#define BB   4
#define SS   4096
#define DD   1024
#define HH   8
#define DK_  128
#define SEG_ 512
#define NSEG 8
#define DH_  4096
#define MROWS (BB*SS)   // 16384
#define QS   3072       // fused qkv row stride

// ---------------- scratch ----------------
__device__ float g_qkv[(size_t)MROWS*QS];
__device__ float g_x1[(size_t)MROWS*DD];
__device__ float g_ff[(size_t)MROWS*DH_];      // reused: FFN1 hi fp16 output
__device__ float g_ms[(size_t)NSEG*BB*HH*DK_*DK_];
__device__ float g_mp[(size_t)NSEG*BB*HH*DK_*DK_];
__device__ float g_zs[(size_t)NSEG*BB*HH*DK_];
__device__ float g_zp[(size_t)NSEG*BB*HH*DK_];
// fp16 split activation buffers [M][1024]
__device__ __half g_ah[(size_t)MROWS*DD];
__device__ __half g_al[(size_t)MROWS*DD];
// transposed fp16 weights [N][K]
__device__ __half g_bqkv[(size_t)QS*DD];
__device__ __half g_bo[(size_t)DD*DD];
__device__ __half g_bw1[(size_t)DH_*DD];
__device__ __half g_bw2[(size_t)DD*DH_];

__device__ __forceinline__ float gelu_f(float x) {
    float x3 = x*x*x;
    float t = tanhf(0.7978845608028654f*(x + 0.044715f*x3));
    return 0.5f*x*(1.f + t);
}

// ================= PTX helpers =================
__device__ __forceinline__ uint32_t smem_u32(const void* p) {
    uint32_t a;
    asm("{ .reg .u64 t; cvta.to.shared.u64 t, %1; cvt.u32.u64 %0, t; }" : "=r"(a) : "l"(p));
    return a;
}
__device__ __forceinline__ void cpa16(uint32_t d, const void* s) {
    asm volatile("cp.async.cg.shared.global [%0], [%1], 16;"
                 :: "r"(d), "l"(__cvta_generic_to_global((void*)s)) : "memory");
}
#define SWZ(x) ((x) ^ (((x) >> 3) & 0x70))

#define LDSM4(r0,r1,r2,r3,addr) \
    asm volatile("ldmatrix.sync.aligned.m8n8.x4.shared.b16 {%0,%1,%2,%3}, [%4];" \
                 : "=r"(r0),"=r"(r1),"=r"(r2),"=r"(r3) : "r"(addr))

#define MMA16816(d, a, b) \
    asm volatile("mma.sync.aligned.m16n8k16.row.col.f32.f16.f16.f32 " \
                 "{%0,%1,%2,%3}, {%4,%5,%6,%7}, {%8,%9}, {%0,%1,%2,%3};" \
                 : "+f"((d)[0]),"+f"((d)[1]),"+f"((d)[2]),"+f"((d)[3]) \
                 : "r"((a)[0]),"r"((a)[1]),"r"((a)[2]),"r"((a)[3]), \
                   "r"((b)[0]),"r"((b)[1]))

// ---------------- LayerNorm -> fp16 hi/lo split ----------------
__global__ void ln_kernel(const float* __restrict__ x, const float* __restrict__ gamma,
                          const float* __restrict__ beta,
                          __half* __restrict__ Ah, __half* __restrict__ Al) {
    __shared__ float s1[256], s2[256];
    const int row = blockIdx.x;
    const int tid = threadIdx.x;
    const float* xr = x + (size_t)row*DD;
    float4 v = *(const float4*)&xr[tid*4];
    float s  = v.x+v.y+v.z+v.w;
    float ss = v.x*v.x+v.y*v.y+v.z*v.z+v.w*v.w;
    s1[tid]=s; s2[tid]=ss; __syncthreads();
    for (int o=128;o>0;o>>=1){ if(tid<o){s1[tid]+=s1[tid+o]; s2[tid]+=s2[tid+o];} __syncthreads(); }
    float mu  = s1[0]*(1.f/DD);
    float var = s2[0]*(1.f/DD) - mu*mu;
    float inv = rsqrtf(var + 1e-5f);
    float4 g  = *(const float4*)&gamma[tid*4];
    float4 bt = *(const float4*)&beta[tid*4];
    float o0 = (v.x-mu)*inv*g.x + bt.x;
    float o1 = (v.y-mu)*inv*g.y + bt.y;
    float o2 = (v.z-mu)*inv*g.z + bt.z;
    float o3 = (v.w-mu)*inv*g.w + bt.w;
    __half h0=__float2half_rn(o0), h1=__float2half_rn(o1), h2=__float2half_rn(o2), h3=__float2half_rn(o3);
    size_t base = (size_t)row*DD + tid*4;
    *(__half2*)&Ah[base]   = __halves2half2(h0, h1);
    *(__half2*)&Ah[base+2] = __halves2half2(h2, h3);
    *(__half2*)&Al[base]   = __halves2half2(__float2half_rn(o0-__half2float(h0)),
                                            __float2half_rn(o1-__half2float(h1)));
    *(__half2*)&Al[base+2] = __halves2half2(__float2half_rn(o2-__half2float(h2)),
                                            __float2half_rn(o3-__half2float(h3)));
}

// ---------------- Weight prep: W[K,N] -> Bp[N][K] fp16 (transposed) ----------------
__global__ void prep_w_kernel(const float* __restrict__ W, __half* __restrict__ Bp,
                              int K, int N) {
    __shared__ float ts[32][33];
    const int n0 = blockIdx.x*32, k0 = blockIdx.y*32;
    const int tx = threadIdx.x, ty = threadIdx.y;   // (32,8)
    #pragma unroll
    for (int i = 0; i < 4; i++)
        ts[ty+8*i][tx] = W[(size_t)(k0+ty+8*i)*N + n0+tx];
    __syncthreads();
    #pragma unroll
    for (int i = 0; i < 4; i++) {
        int nl = ty + 8*i;
        Bp[(size_t)(n0+nl)*K + k0+tx] = __float2half_rn(ts[tx][nl]);
    }
}

// ---------------- mma.sync fp16 GEMM ----------------
// npass=2: virtual 2K loop (Ah then Al, B re-read). npass=1: hi only.
// splitOut: 0 = fp32 C, 1 = fp16 hi+lo, 2 = fp16 hi only.
#define GBK 64
#define NSTG 3
#define STB 16384
#define STAGE_BYTES (2*STB)
#define HG_SMEM (NSTG*STAGE_BYTES)

__global__ __launch_bounds__(256, 2) void hgemm_kernel(
    const __half* __restrict__ Ah, const __half* __restrict__ Al,
    const __half* __restrict__ Bp,
    const float* __restrict__ bias, const float* __restrict__ add,
    float* __restrict__ C, __half* __restrict__ Cah, __half* __restrict__ Cal,
    int M, int N, int K, int act, int splitOut, int npass)
{
    extern __shared__ char dsm[];
    const uint32_t sb = smem_u32(dsm);
    const int tid = threadIdx.x;
    const int lane = tid & 31, wid = tid >> 5;
    const int row0 = blockIdx.y * 128, col0 = blockIdx.x * 128;
    const int NT = npass*K / GBK;

    const int wm = (wid >> 2) * 64;
    const int wn = (wid & 3) * 32;

    float acc[4][4][4];
    #pragma unroll
    for (int i=0;i<4;i++)
        #pragma unroll
        for (int j=0;j<4;j++)
            #pragma unroll
            for (int c=0;c<4;c++) acc[i][j][c]=0.f;

    auto load_tile = [&](int t, int s) {
        int keff = t * GBK;
        const __half* As = (keff < K) ? Ah : Al;
        int k0 = (keff < K) ? keff : keff - K;
        uint32_t stA = sb + s*STAGE_BYTES;
        uint32_t stB = stA + STB;
        #pragma unroll
        for (int i = 0; i < 4; i++) {
            int ch = i*256 + tid;
            int r = ch >> 3, c = (ch & 7) * 8;
            cpa16(stA + SWZ(ch*16), As + (size_t)(row0 + r)*K + k0 + c);
            cpa16(stB + SWZ(ch*16), Bp + (size_t)(col0 + r)*K + k0 + c);
        }
        asm volatile("cp.async.commit_group;" ::: "memory");
    };

    load_tile(0, 0);
    if (NT > 1) load_tile(1, 1);

    const int aRow = wm + (lane & 15);
    const int aColB = ((lane >> 4) & 1) * 16;
    const int bRow = wn + (lane & 7) + ((lane >> 4) & 1) * 8;
    const int bColB = ((lane >> 3) & 1) * 16;

    for (int t = 0; t < NT; t++) {
        if (t < NT-1) asm volatile("cp.async.wait_group 1;" ::: "memory");
        else          asm volatile("cp.async.wait_group 0;" ::: "memory");
        __syncthreads();
        if (t + 2 < NT) load_tile(t + 2, (t + 2) % NSTG);
        uint32_t stA = sb + (t % NSTG)*STAGE_BYTES;
        uint32_t stB = stA + STB;
        #pragma unroll
        for (int kk = 0; kk < 4; kk++) {
            uint32_t af[4][4];
            #pragma unroll
            for (int mt = 0; mt < 4; mt++) {
                uint32_t addr = stA + SWZ((uint32_t)(aRow + mt*16)*128 + kk*32 + aColB);
                LDSM4(af[mt][0], af[mt][1], af[mt][2], af[mt][3], addr);
            }
            uint32_t bf[4][2];
            #pragma unroll
            for (int nt2 = 0; nt2 < 2; nt2++) {
                uint32_t r0,r1,r2,r3;
                uint32_t addr = stB + SWZ((uint32_t)(bRow + nt2*16)*128 + kk*32 + bColB);
                LDSM4(r0, r1, r2, r3, addr);
                bf[nt2*2][0]=r0; bf[nt2*2][1]=r1; bf[nt2*2+1][0]=r2; bf[nt2*2+1][1]=r3;
            }
            #pragma unroll
            for (int mt = 0; mt < 4; mt++)
                #pragma unroll
                for (int nt = 0; nt < 4; nt++)
                    MMA16816(acc[mt][nt], af[mt], bf[nt]);
        }
        __syncthreads();
    }

    const int erow = lane >> 2, ecol = (lane & 3) * 2;
    #pragma unroll
    for (int mt = 0; mt < 4; mt++) {
        #pragma unroll
        for (int half_ = 0; half_ < 2; half_++) {
            int row = row0 + wm + mt*16 + erow + half_*8;
            size_t rbase = (size_t)row * N;
            #pragma unroll
            for (int nt = 0; nt < 4; nt++) {
                int col = col0 + wn + nt*8 + ecol;
                float v0 = acc[mt][nt][half_*2+0];
                float v1 = acc[mt][nt][half_*2+1];
                if (bias) { v0 += bias[col]; v1 += bias[col+1]; }
                if (act)  { v0 = gelu_f(v0); v1 = gelu_f(v1); }
                if (add)  {
                    const float2 a2 = *(const float2*)&add[rbase + col];
                    v0 += a2.x; v1 += a2.y;
                }
                if (splitOut) {
                    __half h0 = __float2half_rn(v0), h1 = __float2half_rn(v1);
                    *(__half2*)&Cah[rbase + col] = __halves2half2(h0, h1);
                    if (splitOut == 1)
                        *(__half2*)&Cal[rbase + col] =
                            __halves2half2(__float2half_rn(v0 - __half2float(h0)),
                                           __float2half_rn(v1 - __half2float(h1)));
                } else {
                    *(float2*)&C[rbase + col] = make_float2(v0, v1);
                }
            }
        }
    }
}

// ---------------- Per-segment memory contributions (stride QS) ----------------
__global__ void segkv_kernel(const float* __restrict__ k, const float* __restrict__ v,
                             float* __restrict__ ms, float* __restrict__ zs)
{
    __shared__ float sks[32][128];
    __shared__ float svs[32][128];
    __shared__ float zacc[128];
    const int seg = blockIdx.x, bh = blockIdx.y;
    const int b = bh >> 3, h = bh & 7;
    const int tid = threadIdx.x;
    const int ty = tid >> 4, tx = tid & 15;
    float acc[8][8];
    #pragma unroll
    for (int i=0;i<8;i++)
        #pragma unroll
        for (int j=0;j<8;j++) acc[i][j]=0.f;
    if (tid < 128) zacc[tid] = 0.f;
    size_t base = ((size_t)b*SS + seg*SEG_)*QS + h*DK_;
    for (int p0 = 0; p0 < SEG_; p0 += 32) {
        __syncthreads();
        for (int i = tid; i < 32*32; i += 256) {
            int row = i >> 5, c4 = (i & 31)*4;
            float4 kv = *(const float4*)&k[base + (size_t)(p0+row)*QS + c4];
            kv.x = kv.x>0.f?kv.x+1.f:__expf(kv.x);
            kv.y = kv.y>0.f?kv.y+1.f:__expf(kv.y);
            kv.z = kv.z>0.f?kv.z+1.f:__expf(kv.z);
            kv.w = kv.w>0.f?kv.w+1.f:__expf(kv.w);
            *(float4*)&sks[row][c4] = kv;
            *(float4*)&svs[row][c4] = *(const float4*)&v[base + (size_t)(p0+row)*QS + c4];
        }
        __syncthreads();
        if (tid < 128) {
            float za = 0.f;
            for (int p = 0; p < 32; p++) za += sks[p][tid];
            zacc[tid] += za;
        }
        #pragma unroll 4
        for (int p = 0; p < 32; p++) {
            float4 k0 = *(const float4*)&sks[p][ty*8];
            float4 k1 = *(const float4*)&sks[p][ty*8+4];
            float4 v0 = *(const float4*)&svs[p][tx*8];
            float4 v1 = *(const float4*)&svs[p][tx*8+4];
            float kr[8] = {k0.x,k0.y,k0.z,k0.w,k1.x,k1.y,k1.z,k1.w};
            float vr[8] = {v0.x,v0.y,v0.z,v0.w,v1.x,v1.y,v1.z,v1.w};
            #pragma unroll
            for (int i=0;i<8;i++)
                #pragma unroll
                for (int j=0;j<8;j++) acc[i][j] += kr[i]*vr[j];
        }
    }
    size_t obase = ((size_t)seg*32 + bh)*DK_*DK_;
    #pragma unroll
    for (int i=0;i<8;i++)
        #pragma unroll
        for (int j=0;j<8;j++)
            ms[obase + (size_t)(ty*8+i)*DK_ + tx*8+j] = acc[i][j];
    if (tid < 128) zs[((size_t)seg*32 + bh)*DK_ + tid] = zacc[tid];
}

// ---------------- Exclusive prefix over 8 segments ----------------
__global__ void prefix_kernel(const float* __restrict__ ms, const float* __restrict__ zs,
                              float* __restrict__ mp, float* __restrict__ zp)
{
    size_t idx = (size_t)blockIdx.x*256 + threadIdx.x;
    const size_t stride = (size_t)BB*HH*DK_*DK_;
    if (idx < stride) {
        float a = 0.f;
        #pragma unroll
        for (int t = 0; t < NSEG; t++) { mp[t*stride + idx] = a; a += ms[t*stride + idx]; }
    }
    if (idx < (size_t)BB*HH*DK_) {
        const size_t zstr = (size_t)BB*HH*DK_;
        float a = 1.f/128.f;
        #pragma unroll
        for (int t = 0; t < NSEG; t++) { zp[t*zstr + idx] = a; a += zs[t*zstr + idx]; }
    }
}

// ---------------- Attention: register-blocked, float4 smem ----------------
#define AP 132
#define SPP 68
#define ATTN_SMEM_FLOATS (64*AP*2 + 64*128 + 64*SPP + 128 + 4*64)
__global__ __launch_bounds__(256, 1) void attn_kernel(
    const float* __restrict__ q, const float* __restrict__ k,
    const float* __restrict__ v, const float* __restrict__ memp,
    const float* __restrict__ zp, const float* __restrict__ betas,
    __half* __restrict__ Oah, __half* __restrict__ Oal)
{
    extern __shared__ float sh[];
    float* Qs  = sh;                 // [64][AP]
    float* Ks  = Qs + 64*AP;         // [64][AP]  (later reused for sq)
    float* Vs  = Ks + 64*AP;         // [64][128] (later reused for M chunks)
    float* Spt = Vs + 64*128;        // [64 c][SPP]
    float* Zs  = Spt + 64*SPP;       // [128]
    float* mrow = Zs + 128;
    float* lrow = mrow + 64;
    float* arow = lrow + 64;
    float* drow = arow + 64;

    const int qt = blockIdx.x, seg = blockIdx.y;
    const int b = blockIdx.z >> 3, h = blockIdx.z & 7;
    const int tid = threadIdx.x;
    const int ty = tid >> 4, tx = tid & 15;

    const float* Z = zp + (((size_t)seg*BB + b)*HH + h)*DK_;
    size_t qbase = ((size_t)b*SS + seg*SEG_ + qt*64)*QS + h*DK_;
    #pragma unroll
    for (int i = tid; i < 64*32; i += 256) {
        int row = i >> 5, c4 = (i & 31)*4;
        *(float4*)&Qs[row*AP + c4] = *(const float4*)&q[qbase + (size_t)row*QS + c4];
    }
    if (tid < 128) Zs[tid] = Z[tid];
    if (tid < 64) { mrow[tid] = -INFINITY; lrow[tid] = 0.f; }
    float o[4][8];
    #pragma unroll
    for (int i=0;i<4;i++)
        #pragma unroll
        for (int j=0;j<8;j++) o[i][j]=0.f;
    __syncthreads();

    const float scale = 0.08838834764831845f;
    for (int kt = 0; kt <= qt; kt++) {
        size_t kbase = ((size_t)b*SS + seg*SEG_ + kt*64)*QS + h*DK_;
        #pragma unroll
        for (int i = tid; i < 64*32; i += 256) {
            int row = i >> 5, c4 = (i & 31)*4;
            *(float4*)&Ks[row*AP + c4] = *(const float4*)&k[kbase + (size_t)row*QS + c4];
            *(float4*)&Vs[row*128 + c4] = *(const float4*)&v[kbase + (size_t)row*QS + c4];
        }
        __syncthreads();

        float s[4][4];
        #pragma unroll
        for (int i=0;i<4;i++)
            #pragma unroll
            for (int j=0;j<4;j++) s[i][j]=0.f;
        #pragma unroll 4
        for (int d = 0; d < 128; d += 4) {
            float4 qv[4], kv[4];
            #pragma unroll
            for (int i=0;i<4;i++) qv[i] = *(const float4*)&Qs[(ty*4+i)*AP + d];
            #pragma unroll
            for (int j=0;j<4;j++) kv[j] = *(const float4*)&Ks[(tx*4+j)*AP + d];
            #pragma unroll
            for (int i=0;i<4;i++)
                #pragma unroll
                for (int j=0;j<4;j++)
                    s[i][j] += qv[i].x*kv[j].x + qv[i].y*kv[j].y
                             + qv[i].z*kv[j].z + qv[i].w*kv[j].w;
        }
        #pragma unroll
        for (int j=0;j<4;j++) {
            int c = tx*4 + j;
            #pragma unroll
            for (int i=0;i<4;i++) {
                int r = ty*4 + i;
                float vv = s[i][j]*scale;
                if (kt == qt && c > r) vv = -INFINITY;
                Spt[c*SPP + r] = vv;
            }
        }
        __syncthreads();

        if (tid < 64) {
            float mold = mrow[tid], mx = mold;
            for (int c = 0; c < 64; c++) mx = fmaxf(mx, Spt[c*SPP + tid]);
            float al = __expf(mold - mx);
            float ls = 0.f;
            for (int c = 0; c < 64; c++) {
                float p = __expf(Spt[c*SPP + tid] - mx);
                Spt[c*SPP + tid] = p; ls += p;
            }
            lrow[tid] = lrow[tid]*al + ls;
            mrow[tid] = mx; arow[tid] = al;
        }
        __syncthreads();

        float a_[4];
        #pragma unroll
        for (int i=0;i<4;i++) a_[i] = arow[ty*4+i];
        #pragma unroll
        for (int i=0;i<4;i++)
            #pragma unroll
            for (int j=0;j<8;j++) o[i][j] *= a_[i];
        #pragma unroll 2
        for (int c = 0; c < 64; c++) {
            float4 p4 = *(const float4*)&Spt[c*SPP + ty*4];
            float pp[4] = {p4.x, p4.y, p4.z, p4.w};
            float4 v0 = *(const float4*)&Vs[c*128 + tx*8];
            float4 v1 = *(const float4*)&Vs[c*128 + tx*8 + 4];
            float vr[8] = {v0.x,v0.y,v0.z,v0.w,v1.x,v1.y,v1.z,v1.w};
            #pragma unroll
            for (int i=0;i<4;i++)
                #pragma unroll
                for (int j=0;j<8;j++) o[i][j] += pp[i]*vr[j];
        }
        __syncthreads();
    }

    #pragma unroll
    for (int i = tid; i < 64*128; i += 256) {
        int row = i >> 7, d = i & 127;
        float qv = Qs[row*AP + d];
        Ks[row*AP + d] = qv > 0.f ? qv + 1.f : __expf(qv);
    }
    __syncthreads();
    if (tid < 64) {
        float ds = 0.f;
        #pragma unroll 4
        for (int d = 0; d < 128; d += 4) {
            float4 sq4 = *(const float4*)&Ks[tid*AP + d];
            float4 z4  = *(const float4*)&Zs[d];
            ds += sq4.x*z4.x + sq4.y*z4.y + sq4.z*z4.z + sq4.w*z4.w;
        }
        drow[tid] = ds;
    }

    const float* M = memp + (((size_t)seg*BB + b)*HH + h)*DK_*DK_;
    float am[4][8];
    #pragma unroll
    for (int i=0;i<4;i++)
        #pragma unroll
        for (int j=0;j<8;j++) am[i][j]=0.f;
    for (int d0 = 0; d0 < 128; d0 += 32) {
        __syncthreads();
        #pragma unroll
        for (int i = tid; i < 32*32; i += 256) {
            int row = i >> 5, c4 = (i & 31)*4;
            *(float4*)&Vs[row*128 + c4] = *(const float4*)&M[(size_t)(d0+row)*128 + c4];
        }
        __syncthreads();
        #pragma unroll 2
        for (int dd = 0; dd < 32; dd += 4) {
            float sqa[4][4];
            #pragma unroll
            for (int i=0;i<4;i++) {
                float4 s4 = *(const float4*)&Ks[(ty*4+i)*AP + d0 + dd];
                sqa[i][0]=s4.x; sqa[i][1]=s4.y; sqa[i][2]=s4.z; sqa[i][3]=s4.w;
            }
            #pragma unroll
            for (int t = 0; t < 4; t++) {
                float4 m0 = *(const float4*)&Vs[(dd+t)*128 + tx*8];
                float4 m1 = *(const float4*)&Vs[(dd+t)*128 + tx*8 + 4];
                float mr[8] = {m0.x,m0.y,m0.z,m0.w,m1.x,m1.y,m1.z,m1.w};
                #pragma unroll
                for (int i=0;i<4;i++)
                    #pragma unroll
                    for (int j=0;j<8;j++) am[i][j] += sqa[i][t]*mr[j];
            }
        }
    }

    float gte[8];
    #pragma unroll
    for (int j=0;j<8;j++)
        gte[j] = 1.f / (1.f + __expf(-betas[h*DK_ + tx*8 + j]));
    #pragma unroll
    for (int i=0;i<4;i++) {
        int r = ty*4 + i;
        float dinv = 1.f / drow[r];
        float linv = 1.f / lrow[r];
        size_t ob = ((size_t)b*SS + seg*SEG_ + qt*64 + r)*DD + h*DK_ + tx*8;
        #pragma unroll
        for (int j=0;j<8;j+=2) {
            float u0 = gte[j]  *(am[i][j]  *dinv) + (1.f-gte[j])  *(o[i][j]  *linv);
            float u1 = gte[j+1]*(am[i][j+1]*dinv) + (1.f-gte[j+1])*(o[i][j+1]*linv);
            __half h0 = __float2half_rn(u0), h1 = __float2half_rn(u1);
            *(__half2*)&Oah[ob + j] = __halves2half2(h0, h1);
            *(__half2*)&Oal[ob + j] = __halves2half2(__float2half_rn(u0-__half2float(h0)),
                                                     __float2half_rn(u1-__half2float(h1)));
        }
    }
}

// ---------------- launch ----------------
extern "C" void kernel_launch(void* const* d_in, const int* in_sizes, int n_in,
                              void* d_out, int out_size)
{
    const float* x     = (const float*)d_in[0];
    const float* ln_g  = (const float*)d_in[1];
    const float* ln_b  = (const float*)d_in[2];
    const float* Wq    = (const float*)d_in[3];
    const float* Wk    = (const float*)d_in[4];
    const float* Wv    = (const float*)d_in[5];
    const float* Wo    = (const float*)d_in[6];
    const float* betas = (const float*)d_in[7];
    const float* w1    = (const float*)d_in[8];
    const float* b1    = (const float*)d_in[9];
    const float* w2    = (const float*)d_in[10];
    const float* b2    = (const float*)d_in[11];
    float* out = (float*)d_out;

    float *qkv, *x1, *ff, *ms, *mp, *zs, *zp;
    __half *ah, *al, *bqkv, *bo, *bw1, *bw2;
    cudaGetSymbolAddress((void**)&qkv, g_qkv);
    cudaGetSymbolAddress((void**)&x1, g_x1);
    cudaGetSymbolAddress((void**)&ff, g_ff);
    cudaGetSymbolAddress((void**)&ms, g_ms);
    cudaGetSymbolAddress((void**)&mp, g_mp);
    cudaGetSymbolAddress((void**)&zs, g_zs);
    cudaGetSymbolAddress((void**)&zp, g_zp);
    cudaGetSymbolAddress((void**)&ah, g_ah);
    cudaGetSymbolAddress((void**)&al, g_al);
    cudaGetSymbolAddress((void**)&bqkv, g_bqkv);
    cudaGetSymbolAddress((void**)&bo, g_bo);
    cudaGetSymbolAddress((void**)&bw1, g_bw1);
    cudaGetSymbolAddress((void**)&bw2, g_bw2);

    __half* ah2 = (__half*)ff;     // FFN1 hi-only output

    const int attn_smem = ATTN_SMEM_FLOATS * 4;
    cudaFuncSetAttribute(attn_kernel, cudaFuncAttributeMaxDynamicSharedMemorySize, attn_smem);
    cudaFuncSetAttribute(hgemm_kernel, cudaFuncAttributeMaxDynamicSharedMemorySize, HG_SMEM);

    dim3 wblk(32, 8);

    // weight prep: fused QKV rows [0:1024)=Wq, [1024:2048)=Wk, [2048:3072)=Wv
    prep_w_kernel<<<dim3(1024/32, 1024/32), wblk>>>(Wq, bqkv,                      1024, 1024);
    prep_w_kernel<<<dim3(1024/32, 1024/32), wblk>>>(Wk, bqkv + (size_t)1024*1024,  1024, 1024);
    prep_w_kernel<<<dim3(1024/32, 1024/32), wblk>>>(Wv, bqkv + (size_t)2048*1024,  1024, 1024);
    prep_w_kernel<<<dim3(1024/32, 1024/32), wblk>>>(Wo, bo, 1024, 1024);
    prep_w_kernel<<<dim3(4096/32, 1024/32), wblk>>>(w1, bw1, 1024, 4096);
    prep_w_kernel<<<dim3(1024/32, 4096/32), wblk>>>(w2, bw2, 4096, 1024);

    // 1) LN1 -> split
    ln_kernel<<<MROWS, 256>>>(x, ln_g, ln_b, ah, al);
    // 2) fused QKV projection (N=3072, 2-pass split)
    hgemm_kernel<<<dim3(QS/128, MROWS/128), 256, HG_SMEM>>>(ah, al, bqkv, nullptr, nullptr,
                                                            qkv, nullptr, nullptr, MROWS, QS, DD, 0, 0, 2);
    // 3-5) infini-attention
    segkv_kernel<<<dim3(NSEG, BB*HH), 256>>>(qkv + 1024, qkv + 2048, ms, zs);
    prefix_kernel<<<(BB*HH*DK_*DK_)/256, 256>>>(ms, zs, mp, zp);
    attn_kernel<<<dim3(8, NSEG, BB*HH), 256, attn_smem>>>(qkv, qkv + 1024, qkv + 2048,
                                                          mp, zp, betas, ah, al);
    // 6) output projection + residual (2-pass split)
    dim3 g1(DD/128, MROWS/128);
    hgemm_kernel<<<g1, 256, HG_SMEM>>>(ah, al, bo, nullptr, x, x1, nullptr, nullptr, MROWS, DD, DD, 0, 0, 2);
    // 7) LN2 -> split
    ln_kernel<<<MROWS, 256>>>(x1, ln_g, ln_b, ah, al);
    // 8) FFN1 + bias + gelu -> hi-only fp16 out (1-pass)
    hgemm_kernel<<<dim3(DH_/128, MROWS/128), 256, HG_SMEM>>>(ah, nullptr, bw1, b1, nullptr, nullptr,
                                                             ah2, nullptr, MROWS, DH_, DD, 1, 2, 1);
    // 9) FFN2 + bias + residual -> out (1-pass, hi input only)
    hgemm_kernel<<<dim3(DD/128, MROWS/128), 256, HG_SMEM>>>(ah2, nullptr, bw2, b2, x1, out,
                                                            nullptr, nullptr, MROWS, DD, DH_, 0, 0, 1);
}

// round 10
// speedup vs baseline: 1.3535x; 1.0645x over previous
#include <cuda_runtime.h>
#include <cuda_fp16.h>
#include <math.h>
#include <stdint.h>

// Problem constants
#define BB   4
#define SS   4096
#define DD   1024
#define HH   8
#define DK_  128
#define SEG_ 512
#define NSEG 8
#define DH_  4096
#define MROWS (BB*SS)   // 16384
#define QS   3072       // fused qkv row stride

// ---------------- scratch ----------------
__device__ float g_qkv[(size_t)MROWS*QS];
__device__ float g_x1[(size_t)MROWS*DD];
__device__ float g_ff[(size_t)MROWS*DH_];      // reused: FFN1 hi fp16 output
__device__ float g_ms[(size_t)NSEG*BB*HH*DK_*DK_];
__device__ float g_mp[(size_t)NSEG*BB*HH*DK_*DK_];
__device__ float g_zs[(size_t)NSEG*BB*HH*DK_];
__device__ float g_zp[(size_t)NSEG*BB*HH*DK_];
// fp16 split activation buffers [M][1024]
__device__ __half g_ah[(size_t)MROWS*DD];
__device__ __half g_al[(size_t)MROWS*DD];
// transposed fp16 weights [N][K]
__device__ __half g_bqkv[(size_t)QS*DD];
__device__ __half g_bo[(size_t)DD*DD];
__device__ __half g_bw1[(size_t)DH_*DD];
__device__ __half g_bw2[(size_t)DD*DH_];

__device__ __forceinline__ float gelu_f(float x) {
    float x3 = x*x*x;
    float t = tanhf(0.7978845608028654f*(x + 0.044715f*x3));
    return 0.5f*x*(1.f + t);
}

// ================= PTX helpers =================
__device__ __forceinline__ uint32_t smem_u32(const void* p) {
    uint32_t a;
    asm("{ .reg .u64 t; cvta.to.shared.u64 t, %1; cvt.u32.u64 %0, t; }" : "=r"(a) : "l"(p));
    return a;
}
__device__ __forceinline__ void cpa16(uint32_t d, const void* s) {
    asm volatile("cp.async.cg.shared.global [%0], [%1], 16;"
                 :: "r"(d), "l"(__cvta_generic_to_global((void*)s)) : "memory");
}
#define SWZ(x) ((x) ^ (((x) >> 3) & 0x70))

#define LDSM4(r0,r1,r2,r3,addr) \
    asm volatile("ldmatrix.sync.aligned.m8n8.x4.shared.b16 {%0,%1,%2,%3}, [%4];" \
                 : "=r"(r0),"=r"(r1),"=r"(r2),"=r"(r3) : "r"(addr))

#define MMA16816(d, a, b) \
    asm volatile("mma.sync.aligned.m16n8k16.row.col.f32.f16.f16.f32 " \
                 "{%0,%1,%2,%3}, {%4,%5,%6,%7}, {%8,%9}, {%0,%1,%2,%3};" \
                 : "+f"((d)[0]),"+f"((d)[1]),"+f"((d)[2]),"+f"((d)[3]) \
                 : "r"((a)[0]),"r"((a)[1]),"r"((a)[2]),"r"((a)[3]), \
                   "r"((b)[0]),"r"((b)[1]))

// ---------------- LayerNorm -> fp16 hi/lo split ----------------
__global__ void ln_kernel(const float* __restrict__ x, const float* __restrict__ gamma,
                          const float* __restrict__ beta,
                          __half* __restrict__ Ah, __half* __restrict__ Al) {
    __shared__ float s1[256], s2[256];
    const int row = blockIdx.x;
    const int tid = threadIdx.x;
    const float* xr = x + (size_t)row*DD;
    float4 v = *(const float4*)&xr[tid*4];
    float s  = v.x+v.y+v.z+v.w;
    float ss = v.x*v.x+v.y*v.y+v.z*v.z+v.w*v.w;
    s1[tid]=s; s2[tid]=ss; __syncthreads();
    for (int o=128;o>0;o>>=1){ if(tid<o){s1[tid]+=s1[tid+o]; s2[tid]+=s2[tid+o];} __syncthreads(); }
    float mu  = s1[0]*(1.f/DD);
    float var = s2[0]*(1.f/DD) - mu*mu;
    float inv = rsqrtf(var + 1e-5f);
    float4 g  = *(const float4*)&gamma[tid*4];
    float4 bt = *(const float4*)&beta[tid*4];
    float o0 = (v.x-mu)*inv*g.x + bt.x;
    float o1 = (v.y-mu)*inv*g.y + bt.y;
    float o2 = (v.z-mu)*inv*g.z + bt.z;
    float o3 = (v.w-mu)*inv*g.w + bt.w;
    __half h0=__float2half_rn(o0), h1=__float2half_rn(o1), h2=__float2half_rn(o2), h3=__float2half_rn(o3);
    size_t base = (size_t)row*DD + tid*4;
    *(__half2*)&Ah[base]   = __halves2half2(h0, h1);
    *(__half2*)&Ah[base+2] = __halves2half2(h2, h3);
    *(__half2*)&Al[base]   = __halves2half2(__float2half_rn(o0-__half2float(h0)),
                                            __float2half_rn(o1-__half2float(h1)));
    *(__half2*)&Al[base+2] = __halves2half2(__float2half_rn(o2-__half2float(h2)),
                                            __float2half_rn(o3-__half2float(h3)));
}

// ---------------- Weight prep: W[K,N] -> Bp[N][K] fp16 (transposed) ----------------
__global__ void prep_w_kernel(const float* __restrict__ W, __half* __restrict__ Bp,
                              int K, int N) {
    __shared__ float ts[32][33];
    const int n0 = blockIdx.x*32, k0 = blockIdx.y*32;
    const int tx = threadIdx.x, ty = threadIdx.y;   // (32,8)
    #pragma unroll
    for (int i = 0; i < 4; i++)
        ts[ty+8*i][tx] = W[(size_t)(k0+ty+8*i)*N + n0+tx];
    __syncthreads();
    #pragma unroll
    for (int i = 0; i < 4; i++) {
        int nl = ty + 8*i;
        Bp[(size_t)(n0+nl)*K + k0+tx] = __float2half_rn(ts[tx][nl]);
    }
}

// ---------------- mma.sync fp16 GEMM ----------------
// npass=2: virtual 2K loop (Ah then Al, B re-read). npass=1: hi only.
// splitOut: 0 = fp32 C, 1 = fp16 hi+lo, 2 = fp16 hi only.
// ldc: row stride for C/Cah/Cal/add (supports sub-GEMM column slices).
#define GBK 64
#define NSTG 3
#define STB 16384
#define STAGE_BYTES (2*STB)
#define HG_SMEM (NSTG*STAGE_BYTES)

__global__ __launch_bounds__(256, 2) void hgemm_kernel(
    const __half* __restrict__ Ah, const __half* __restrict__ Al,
    const __half* __restrict__ Bp,
    const float* __restrict__ bias, const float* __restrict__ add,
    float* __restrict__ C, __half* __restrict__ Cah, __half* __restrict__ Cal,
    int M, int N, int ldc, int K, int act, int splitOut, int npass)
{
    extern __shared__ char dsm[];
    const uint32_t sb = smem_u32(dsm);
    const int tid = threadIdx.x;
    const int lane = tid & 31, wid = tid >> 5;
    const int row0 = blockIdx.y * 128, col0 = blockIdx.x * 128;
    const int NT = npass*K / GBK;

    const int wm = (wid >> 2) * 64;
    const int wn = (wid & 3) * 32;

    float acc[4][4][4];
    #pragma unroll
    for (int i=0;i<4;i++)
        #pragma unroll
        for (int j=0;j<4;j++)
            #pragma unroll
            for (int c=0;c<4;c++) acc[i][j][c]=0.f;

    auto load_tile = [&](int t, int s) {
        int keff = t * GBK;
        const __half* As = (keff < K) ? Ah : Al;
        int k0 = (keff < K) ? keff : keff - K;
        uint32_t stA = sb + s*STAGE_BYTES;
        uint32_t stB = stA + STB;
        #pragma unroll
        for (int i = 0; i < 4; i++) {
            int ch = i*256 + tid;
            int r = ch >> 3, c = (ch & 7) * 8;
            cpa16(stA + SWZ(ch*16), As + (size_t)(row0 + r)*K + k0 + c);
            cpa16(stB + SWZ(ch*16), Bp + (size_t)(col0 + r)*K + k0 + c);
        }
        asm volatile("cp.async.commit_group;" ::: "memory");
    };

    load_tile(0, 0);
    if (NT > 1) load_tile(1, 1);

    const int aRow = wm + (lane & 15);
    const int aColB = ((lane >> 4) & 1) * 16;
    const int bRow = wn + (lane & 7) + ((lane >> 4) & 1) * 8;
    const int bColB = ((lane >> 3) & 1) * 16;

    for (int t = 0; t < NT; t++) {
        if (t < NT-1) asm volatile("cp.async.wait_group 1;" ::: "memory");
        else          asm volatile("cp.async.wait_group 0;" ::: "memory");
        __syncthreads();
        if (t + 2 < NT) load_tile(t + 2, (t + 2) % NSTG);
        uint32_t stA = sb + (t % NSTG)*STAGE_BYTES;
        uint32_t stB = stA + STB;
        #pragma unroll
        for (int kk = 0; kk < 4; kk++) {
            uint32_t af[4][4];
            #pragma unroll
            for (int mt = 0; mt < 4; mt++) {
                uint32_t addr = stA + SWZ((uint32_t)(aRow + mt*16)*128 + kk*32 + aColB);
                LDSM4(af[mt][0], af[mt][1], af[mt][2], af[mt][3], addr);
            }
            uint32_t bf[4][2];
            #pragma unroll
            for (int nt2 = 0; nt2 < 2; nt2++) {
                uint32_t r0,r1,r2,r3;
                uint32_t addr = stB + SWZ((uint32_t)(bRow + nt2*16)*128 + kk*32 + bColB);
                LDSM4(r0, r1, r2, r3, addr);
                bf[nt2*2][0]=r0; bf[nt2*2][1]=r1; bf[nt2*2+1][0]=r2; bf[nt2*2+1][1]=r3;
            }
            #pragma unroll
            for (int mt = 0; mt < 4; mt++)
                #pragma unroll
                for (int nt = 0; nt < 4; nt++)
                    MMA16816(acc[mt][nt], af[mt], bf[nt]);
        }
        __syncthreads();
    }

    const int erow = lane >> 2, ecol = (lane & 3) * 2;
    #pragma unroll
    for (int mt = 0; mt < 4; mt++) {
        #pragma unroll
        for (int half_ = 0; half_ < 2; half_++) {
            int row = row0 + wm + mt*16 + erow + half_*8;
            size_t rbase = (size_t)row * ldc;
            #pragma unroll
            for (int nt = 0; nt < 4; nt++) {
                int col = col0 + wn + nt*8 + ecol;
                float v0 = acc[mt][nt][half_*2+0];
                float v1 = acc[mt][nt][half_*2+1];
                if (bias) { v0 += bias[col]; v1 += bias[col+1]; }
                if (act)  { v0 = gelu_f(v0); v1 = gelu_f(v1); }
                if (add)  {
                    const float2 a2 = *(const float2*)&add[rbase + col];
                    v0 += a2.x; v1 += a2.y;
                }
                if (splitOut) {
                    __half h0 = __float2half_rn(v0), h1 = __float2half_rn(v1);
                    *(__half2*)&Cah[rbase + col] = __halves2half2(h0, h1);
                    if (splitOut == 1)
                        *(__half2*)&Cal[rbase + col] =
                            __halves2half2(__float2half_rn(v0 - __half2float(h0)),
                                           __float2half_rn(v1 - __half2float(h1)));
                } else {
                    *(float2*)&C[rbase + col] = make_float2(v0, v1);
                }
            }
        }
    }
}

// ---------------- Per-segment memory contributions (stride QS) ----------------
__global__ void segkv_kernel(const float* __restrict__ k, const float* __restrict__ v,
                             float* __restrict__ ms, float* __restrict__ zs)
{
    __shared__ float sks[32][128];
    __shared__ float svs[32][128];
    __shared__ float zacc[128];
    const int seg = blockIdx.x, bh = blockIdx.y;
    const int b = bh >> 3, h = bh & 7;
    const int tid = threadIdx.x;
    const int ty = tid >> 4, tx = tid & 15;
    float acc[8][8];
    #pragma unroll
    for (int i=0;i<8;i++)
        #pragma unroll
        for (int j=0;j<8;j++) acc[i][j]=0.f;
    if (tid < 128) zacc[tid] = 0.f;
    size_t base = ((size_t)b*SS + seg*SEG_)*QS + h*DK_;
    for (int p0 = 0; p0 < SEG_; p0 += 32) {
        __syncthreads();
        for (int i = tid; i < 32*32; i += 256) {
            int row = i >> 5, c4 = (i & 31)*4;
            float4 kv = *(const float4*)&k[base + (size_t)(p0+row)*QS + c4];
            kv.x = kv.x>0.f?kv.x+1.f:__expf(kv.x);
            kv.y = kv.y>0.f?kv.y+1.f:__expf(kv.y);
            kv.z = kv.z>0.f?kv.z+1.f:__expf(kv.z);
            kv.w = kv.w>0.f?kv.w+1.f:__expf(kv.w);
            *(float4*)&sks[row][c4] = kv;
            *(float4*)&svs[row][c4] = *(const float4*)&v[base + (size_t)(p0+row)*QS + c4];
        }
        __syncthreads();
        if (tid < 128) {
            float za = 0.f;
            for (int p = 0; p < 32; p++) za += sks[p][tid];
            zacc[tid] += za;
        }
        #pragma unroll 4
        for (int p = 0; p < 32; p++) {
            float4 k0 = *(const float4*)&sks[p][ty*8];
            float4 k1 = *(const float4*)&sks[p][ty*8+4];
            float4 v0 = *(const float4*)&svs[p][tx*8];
            float4 v1 = *(const float4*)&svs[p][tx*8+4];
            float kr[8] = {k0.x,k0.y,k0.z,k0.w,k1.x,k1.y,k1.z,k1.w};
            float vr[8] = {v0.x,v0.y,v0.z,v0.w,v1.x,v1.y,v1.z,v1.w};
            #pragma unroll
            for (int i=0;i<8;i++)
                #pragma unroll
                for (int j=0;j<8;j++) acc[i][j] += kr[i]*vr[j];
        }
    }
    size_t obase = ((size_t)seg*32 + bh)*DK_*DK_;
    #pragma unroll
    for (int i=0;i<8;i++)
        #pragma unroll
        for (int j=0;j<8;j++)
            ms[obase + (size_t)(ty*8+i)*DK_ + tx*8+j] = acc[i][j];
    if (tid < 128) zs[((size_t)seg*32 + bh)*DK_ + tid] = zacc[tid];
}

// ---------------- Exclusive prefix over 8 segments ----------------
__global__ void prefix_kernel(const float* __restrict__ ms, const float* __restrict__ zs,
                              float* __restrict__ mp, float* __restrict__ zp)
{
    size_t idx = (size_t)blockIdx.x*256 + threadIdx.x;
    const size_t stride = (size_t)BB*HH*DK_*DK_;
    if (idx < stride) {
        float a = 0.f;
        #pragma unroll
        for (int t = 0; t < NSEG; t++) { mp[t*stride + idx] = a; a += ms[t*stride + idx]; }
    }
    if (idx < (size_t)BB*HH*DK_) {
        const size_t zstr = (size_t)BB*HH*DK_;
        float a = 1.f/128.f;
        #pragma unroll
        for (int t = 0; t < NSEG; t++) { zp[t*zstr + idx] = a; a += zs[t*zstr + idx]; }
    }
}

// ---------------- Attention: register-blocked + shuffle softmax ----------------
#define AP 132
#define SPP 68
#define ATTN_SMEM_FLOATS (64*AP*2 + 64*128 + 64*SPP + 128 + 3*64)
__global__ __launch_bounds__(256, 1) void attn_kernel(
    const float* __restrict__ q, const float* __restrict__ k,
    const float* __restrict__ v, const float* __restrict__ memp,
    const float* __restrict__ zp, const float* __restrict__ betas,
    __half* __restrict__ Oah)
{
    extern __shared__ float sh[];
    float* Qs  = sh;                 // [64][AP]
    float* Ks  = Qs + 64*AP;         // [64][AP]  (later reused for sq)
    float* Vs  = Ks + 64*AP;         // [64][128] (later reused for M chunks)
    float* Spt = Vs + 64*128;        // [64 c][SPP]
    float* Zs  = Spt + 64*SPP;       // [128]
    float* mrow = Zs + 128;
    float* lrow = mrow + 64;
    float* drow = lrow + 64;

    const int qt = blockIdx.x, seg = blockIdx.y;
    const int b = blockIdx.z >> 3, h = blockIdx.z & 7;
    const int tid = threadIdx.x;
    const int ty = tid >> 4, tx = tid & 15;

    const float* Z = zp + (((size_t)seg*BB + b)*HH + h)*DK_;
    size_t qbase = ((size_t)b*SS + seg*SEG_ + qt*64)*QS + h*DK_;
    #pragma unroll
    for (int i = tid; i < 64*32; i += 256) {
        int row = i >> 5, c4 = (i & 31)*4;
        *(float4*)&Qs[row*AP + c4] = *(const float4*)&q[qbase + (size_t)row*QS + c4];
    }
    if (tid < 128) Zs[tid] = Z[tid];
    if (tid < 64) { mrow[tid] = -INFINITY; lrow[tid] = 0.f; }
    float o[4][8];
    #pragma unroll
    for (int i=0;i<4;i++)
        #pragma unroll
        for (int j=0;j<8;j++) o[i][j]=0.f;
    __syncthreads();

    const float scale = 0.08838834764831845f;
    for (int kt = 0; kt <= qt; kt++) {
        size_t kbase = ((size_t)b*SS + seg*SEG_ + kt*64)*QS + h*DK_;
        #pragma unroll
        for (int i = tid; i < 64*32; i += 256) {
            int row = i >> 5, c4 = (i & 31)*4;
            *(float4*)&Ks[row*AP + c4] = *(const float4*)&k[kbase + (size_t)row*QS + c4];
            *(float4*)&Vs[row*128 + c4] = *(const float4*)&v[kbase + (size_t)row*QS + c4];
        }
        __syncthreads();

        // S = Q @ K^T (4x4 per thread)
        float s[4][4];
        #pragma unroll
        for (int i=0;i<4;i++)
            #pragma unroll
            for (int j=0;j<4;j++) s[i][j]=0.f;
        #pragma unroll 4
        for (int d = 0; d < 128; d += 4) {
            float4 qv[4], kv[4];
            #pragma unroll
            for (int i=0;i<4;i++) qv[i] = *(const float4*)&Qs[(ty*4+i)*AP + d];
            #pragma unroll
            for (int j=0;j<4;j++) kv[j] = *(const float4*)&Ks[(tx*4+j)*AP + d];
            #pragma unroll
            for (int i=0;i<4;i++)
                #pragma unroll
                for (int j=0;j<4;j++)
                    s[i][j] += qv[i].x*kv[j].x + qv[i].y*kv[j].y
                             + qv[i].z*kv[j].z + qv[i].w*kv[j].w;
        }
        // scale + causal mask in registers
        #pragma unroll
        for (int i=0;i<4;i++)
            #pragma unroll
            for (int j=0;j<4;j++) {
                float vv = s[i][j]*scale;
                if (kt == qt && (tx*4+j) > (ty*4+i)) vv = -INFINITY;
                s[i][j] = vv;
            }

        // register+shuffle softmax stats (16-lane butterfly across tx)
        float al_[4], ls_[4], mx_[4];
        #pragma unroll
        for (int i=0;i<4;i++) {
            float rm = fmaxf(fmaxf(s[i][0],s[i][1]), fmaxf(s[i][2],s[i][3]));
            #pragma unroll
            for (int off = 1; off < 16; off <<= 1)
                rm = fmaxf(rm, __shfl_xor_sync(0xffffffffu, rm, off));
            float mold = mrow[ty*4+i];
            float mx = fmaxf(mold, rm);
            mx_[i] = mx;
            al_[i] = __expf(mold - mx);
            float ps = 0.f;
            #pragma unroll
            for (int j=0;j<4;j++) {
                float p = __expf(s[i][j] - mx);
                Spt[(tx*4+j)*SPP + ty*4+i] = p;
                ps += p;
            }
            #pragma unroll
            for (int off = 1; off < 16; off <<= 1)
                ps += __shfl_xor_sync(0xffffffffu, ps, off);
            ls_[i] = ps;
        }
        __syncthreads();   // Spt visible; all mrow reads done
        if (tx == 0) {
            #pragma unroll
            for (int i=0;i<4;i++) {
                int r = ty*4 + i;
                mrow[r] = mx_[i];
                lrow[r] = lrow[r]*al_[i] + ls_[i];
            }
        }

        // rescale + PV
        #pragma unroll
        for (int i=0;i<4;i++)
            #pragma unroll
            for (int j=0;j<8;j++) o[i][j] *= al_[i];
        #pragma unroll 2
        for (int c = 0; c < 64; c++) {
            float4 p4 = *(const float4*)&Spt[c*SPP + ty*4];
            float pp[4] = {p4.x, p4.y, p4.z, p4.w};
            float4 v0 = *(const float4*)&Vs[c*128 + tx*8];
            float4 v1 = *(const float4*)&Vs[c*128 + tx*8 + 4];
            float vr[8] = {v0.x,v0.y,v0.z,v0.w,v1.x,v1.y,v1.z,v1.w};
            #pragma unroll
            for (int i=0;i<4;i++)
                #pragma unroll
                for (int j=0;j<8;j++) o[i][j] += pp[i]*vr[j];
        }
        __syncthreads();   // mrow/lrow writes visible; Ks/Vs safe to overwrite
    }

    // ---- retrieval: sq = elu(q)+1 into Ks ----
    #pragma unroll
    for (int i = tid; i < 64*128; i += 256) {
        int row = i >> 7, d = i & 127;
        float qv = Qs[row*AP + d];
        Ks[row*AP + d] = qv > 0.f ? qv + 1.f : __expf(qv);
    }
    __syncthreads();
    if (tid < 64) {
        float ds = 0.f;
        #pragma unroll 4
        for (int d = 0; d < 128; d += 4) {
            float4 sq4 = *(const float4*)&Ks[tid*AP + d];
            float4 z4  = *(const float4*)&Zs[d];
            ds += sq4.x*z4.x + sq4.y*z4.y + sq4.z*z4.z + sq4.w*z4.w;
        }
        drow[tid] = ds;
    }

    const float* M = memp + (((size_t)seg*BB + b)*HH + h)*DK_*DK_;
    float am[4][8];
    #pragma unroll
    for (int i=0;i<4;i++)
        #pragma unroll
        for (int j=0;j<8;j++) am[i][j]=0.f;
    for (int d0 = 0; d0 < 128; d0 += 32) {
        __syncthreads();
        #pragma unroll
        for (int i = tid; i < 32*32; i += 256) {
            int row = i >> 5, c4 = (i & 31)*4;
            *(float4*)&Vs[row*128 + c4] = *(const float4*)&M[(size_t)(d0+row)*128 + c4];
        }
        __syncthreads();
        #pragma unroll 2
        for (int dd = 0; dd < 32; dd += 4) {
            float sqa[4][4];
            #pragma unroll
            for (int i=0;i<4;i++) {
                float4 s4 = *(const float4*)&Ks[(ty*4+i)*AP + d0 + dd];
                sqa[i][0]=s4.x; sqa[i][1]=s4.y; sqa[i][2]=s4.z; sqa[i][3]=s4.w;
            }
            #pragma unroll
            for (int t = 0; t < 4; t++) {
                float4 m0 = *(const float4*)&Vs[(dd+t)*128 + tx*8];
                float4 m1 = *(const float4*)&Vs[(dd+t)*128 + tx*8 + 4];
                float mr[8] = {m0.x,m0.y,m0.z,m0.w,m1.x,m1.y,m1.z,m1.w};
                #pragma unroll
                for (int i=0;i<4;i++)
                    #pragma unroll
                    for (int j=0;j<8;j++) am[i][j] += sqa[i][t]*mr[j];
            }
        }
    }

    // ---- gate + write hi-only fp16 output (row stride DD) ----
    float gte[8];
    #pragma unroll
    for (int j=0;j<8;j++)
        gte[j] = 1.f / (1.f + __expf(-betas[h*DK_ + tx*8 + j]));
    #pragma unroll
    for (int i=0;i<4;i++) {
        int r = ty*4 + i;
        float dinv = 1.f / drow[r];
        float linv = 1.f / lrow[r];
        size_t ob = ((size_t)b*SS + seg*SEG_ + qt*64 + r)*DD + h*DK_ + tx*8;
        #pragma unroll
        for (int j=0;j<8;j+=2) {
            float u0 = gte[j]  *(am[i][j]  *dinv) + (1.f-gte[j])  *(o[i][j]  *linv);
            float u1 = gte[j+1]*(am[i][j+1]*dinv) + (1.f-gte[j+1])*(o[i][j+1]*linv);
            *(__half2*)&Oah[ob + j] = __halves2half2(__float2half_rn(u0), __float2half_rn(u1));
        }
    }
}

// ---------------- launch ----------------
extern "C" void kernel_launch(void* const* d_in, const int* in_sizes, int n_in,
                              void* d_out, int out_size)
{
    const float* x     = (const float*)d_in[0];
    const float* ln_g  = (const float*)d_in[1];
    const float* ln_b  = (const float*)d_in[2];
    const float* Wq    = (const float*)d_in[3];
    const float* Wk    = (const float*)d_in[4];
    const float* Wv    = (const float*)d_in[5];
    const float* Wo    = (const float*)d_in[6];
    const float* betas = (const float*)d_in[7];
    const float* w1    = (const float*)d_in[8];
    const float* b1    = (const float*)d_in[9];
    const float* w2    = (const float*)d_in[10];
    const float* b2    = (const float*)d_in[11];
    float* out = (float*)d_out;

    float *qkv, *x1, *ff, *ms, *mp, *zs, *zp;
    __half *ah, *al, *bqkv, *bo, *bw1, *bw2;
    cudaGetSymbolAddress((void**)&qkv, g_qkv);
    cudaGetSymbolAddress((void**)&x1, g_x1);
    cudaGetSymbolAddress((void**)&ff, g_ff);
    cudaGetSymbolAddress((void**)&ms, g_ms);
    cudaGetSymbolAddress((void**)&mp, g_mp);
    cudaGetSymbolAddress((void**)&zs, g_zs);
    cudaGetSymbolAddress((void**)&zp, g_zp);
    cudaGetSymbolAddress((void**)&ah, g_ah);
    cudaGetSymbolAddress((void**)&al, g_al);
    cudaGetSymbolAddress((void**)&bqkv, g_bqkv);
    cudaGetSymbolAddress((void**)&bo, g_bo);
    cudaGetSymbolAddress((void**)&bw1, g_bw1);
    cudaGetSymbolAddress((void**)&bw2, g_bw2);

    __half* ah2 = (__half*)ff;     // FFN1 hi-only output

    const int attn_smem = ATTN_SMEM_FLOATS * 4;
    cudaFuncSetAttribute(attn_kernel, cudaFuncAttributeMaxDynamicSharedMemorySize, attn_smem);
    cudaFuncSetAttribute(hgemm_kernel, cudaFuncAttributeMaxDynamicSharedMemorySize, HG_SMEM);

    dim3 wblk(32, 8);

    // weight prep: fused QKV rows [0:1024)=Wq, [1024:2048)=Wk, [2048:3072)=Wv
    prep_w_kernel<<<dim3(1024/32, 1024/32), wblk>>>(Wq, bqkv,                      1024, 1024);
    prep_w_kernel<<<dim3(1024/32, 1024/32), wblk>>>(Wk, bqkv + (size_t)1024*1024,  1024, 1024);
    prep_w_kernel<<<dim3(1024/32, 1024/32), wblk>>>(Wv, bqkv + (size_t)2048*1024,  1024, 1024);
    prep_w_kernel<<<dim3(1024/32, 1024/32), wblk>>>(Wo, bo, 1024, 1024);
    prep_w_kernel<<<dim3(4096/32, 1024/32), wblk>>>(w1, bw1, 1024, 4096);
    prep_w_kernel<<<dim3(1024/32, 4096/32), wblk>>>(w2, bw2, 4096, 1024);

    // 1) LN1 -> split
    ln_kernel<<<MROWS, 256>>>(x, ln_g, ln_b, ah, al);
    // 2a) QK projection (N=2048, 2-pass split)
    hgemm_kernel<<<dim3(2048/128, MROWS/128), 256, HG_SMEM>>>(ah, al, bqkv, nullptr, nullptr,
                                                              qkv, nullptr, nullptr,
                                                              MROWS, 2048, QS, DD, 0, 0, 2);
    // 2b) V projection (N=1024, 1-pass hi-only)
    hgemm_kernel<<<dim3(1024/128, MROWS/128), 256, HG_SMEM>>>(ah, nullptr, bqkv + (size_t)2048*1024,
                                                              nullptr, nullptr,
                                                              qkv + 2048, nullptr, nullptr,
                                                              MROWS, 1024, QS, DD, 0, 0, 1);
    // 3-5) infini-attention
    segkv_kernel<<<dim3(NSEG, BB*HH), 256>>>(qkv + 1024, qkv + 2048, ms, zs);
    prefix_kernel<<<(BB*HH*DK_*DK_)/256, 256>>>(ms, zs, mp, zp);
    attn_kernel<<<dim3(8, NSEG, BB*HH), 256, attn_smem>>>(qkv, qkv + 1024, qkv + 2048,
                                                          mp, zp, betas, ah);
    // 6) output projection + residual (1-pass hi-only input)
    dim3 g1(DD/128, MROWS/128);
    hgemm_kernel<<<g1, 256, HG_SMEM>>>(ah, nullptr, bo, nullptr, x, x1, nullptr, nullptr,
                                       MROWS, DD, DD, DD, 0, 0, 1);
    // 7) LN2 -> split
    ln_kernel<<<MROWS, 256>>>(x1, ln_g, ln_b, ah, al);
    // 8) FFN1 + bias + gelu -> hi-only fp16 out (1-pass)
    hgemm_kernel<<<dim3(DH_/128, MROWS/128), 256, HG_SMEM>>>(ah, nullptr, bw1, b1, nullptr, nullptr,
                                                             ah2, nullptr, MROWS, DH_, DH_, DD, 1, 2, 1);
    // 9) FFN2 + bias + residual -> out (1-pass, hi input only)
    hgemm_kernel<<<dim3(DD/128, MROWS/128), 256, HG_SMEM>>>(ah2, nullptr, bw2, b2, x1, out,
                                                            nullptr, nullptr, MROWS, DD, DD, DH_, 0, 0, 1);
}

// round 11
// speedup vs baseline: 1.4377x; 1.0623x over previous
#include <cuda_runtime.h>
#include <cuda_fp16.h>
#include <math.h>
#include <stdint.h>

// Problem constants
#define BB   4
#define SS   4096
#define DD   1024
#define HH   8
#define DK_  128
#define SEG_ 512
#define NSEG 8
#define DH_  4096
#define MROWS (BB*SS)   // 16384
#define QS   3072       // fused qkv row stride

// ---------------- scratch ----------------
__device__ float g_qkv[(size_t)MROWS*QS];
__device__ float g_x1[(size_t)MROWS*DD];
__device__ float g_ff[(size_t)MROWS*DH_];      // reused: FFN1 hi fp16 output
__device__ float g_ms[(size_t)NSEG*BB*HH*DK_*DK_];
__device__ float g_mp[(size_t)NSEG*BB*HH*DK_*DK_];
__device__ float g_zs[(size_t)NSEG*BB*HH*DK_];
__device__ float g_zp[(size_t)NSEG*BB*HH*DK_];
// fp16 activation buffer [M][1024] (hi only)
__device__ __half g_ah[(size_t)MROWS*DD];
// transposed fp16 weights [N][K]
__device__ __half g_bqkv[(size_t)QS*DD];
__device__ __half g_bo[(size_t)DD*DD];
__device__ __half g_bw1[(size_t)DH_*DD];
__device__ __half g_bw2[(size_t)DD*DH_];

__device__ __forceinline__ float gelu_f(float x) {
    float x3 = x*x*x;
    float t = tanhf(0.7978845608028654f*(x + 0.044715f*x3));
    return 0.5f*x*(1.f + t);
}

// ================= PTX helpers =================
__device__ __forceinline__ uint32_t smem_u32(const void* p) {
    uint32_t a;
    asm("{ .reg .u64 t; cvta.to.shared.u64 t, %1; cvt.u32.u64 %0, t; }" : "=r"(a) : "l"(p));
    return a;
}
__device__ __forceinline__ void cpa16(uint32_t d, const void* s) {
    asm volatile("cp.async.cg.shared.global [%0], [%1], 16;"
                 :: "r"(d), "l"(__cvta_generic_to_global((void*)s)) : "memory");
}
#define SWZ(x) ((x) ^ (((x) >> 3) & 0x70))

#define LDSM4(r0,r1,r2,r3,addr) \
    asm volatile("ldmatrix.sync.aligned.m8n8.x4.shared.b16 {%0,%1,%2,%3}, [%4];" \
                 : "=r"(r0),"=r"(r1),"=r"(r2),"=r"(r3) : "r"(addr))

#define MMA16816(d, a, b) \
    asm volatile("mma.sync.aligned.m16n8k16.row.col.f32.f16.f16.f32 " \
                 "{%0,%1,%2,%3}, {%4,%5,%6,%7}, {%8,%9}, {%0,%1,%2,%3};" \
                 : "+f"((d)[0]),"+f"((d)[1]),"+f"((d)[2]),"+f"((d)[3]) \
                 : "r"((a)[0]),"r"((a)[1]),"r"((a)[2]),"r"((a)[3]), \
                   "r"((b)[0]),"r"((b)[1]))

// ---------------- LayerNorm -> fp16 (hi only) ----------------
__global__ void ln_kernel(const float* __restrict__ x, const float* __restrict__ gamma,
                          const float* __restrict__ beta, __half* __restrict__ Ah) {
    __shared__ float s1[256], s2[256];
    const int row = blockIdx.x;
    const int tid = threadIdx.x;
    const float* xr = x + (size_t)row*DD;
    float4 v = *(const float4*)&xr[tid*4];
    float s  = v.x+v.y+v.z+v.w;
    float ss = v.x*v.x+v.y*v.y+v.z*v.z+v.w*v.w;
    s1[tid]=s; s2[tid]=ss; __syncthreads();
    for (int o=128;o>0;o>>=1){ if(tid<o){s1[tid]+=s1[tid+o]; s2[tid]+=s2[tid+o];} __syncthreads(); }
    float mu  = s1[0]*(1.f/DD);
    float var = s2[0]*(1.f/DD) - mu*mu;
    float inv = rsqrtf(var + 1e-5f);
    float4 g  = *(const float4*)&gamma[tid*4];
    float4 bt = *(const float4*)&beta[tid*4];
    float o0 = (v.x-mu)*inv*g.x + bt.x;
    float o1 = (v.y-mu)*inv*g.y + bt.y;
    float o2 = (v.z-mu)*inv*g.z + bt.z;
    float o3 = (v.w-mu)*inv*g.w + bt.w;
    size_t base = (size_t)row*DD + tid*4;
    *(__half2*)&Ah[base]   = __halves2half2(__float2half_rn(o0), __float2half_rn(o1));
    *(__half2*)&Ah[base+2] = __halves2half2(__float2half_rn(o2), __float2half_rn(o3));
}

// ---------------- Weight prep: W[K,N] -> Bp[N][K] fp16 (transposed) ----------------
__global__ void prep_w_kernel(const float* __restrict__ W, __half* __restrict__ Bp,
                              int K, int N) {
    __shared__ float ts[32][33];
    const int n0 = blockIdx.x*32, k0 = blockIdx.y*32;
    const int tx = threadIdx.x, ty = threadIdx.y;   // (32,8)
    #pragma unroll
    for (int i = 0; i < 4; i++)
        ts[ty+8*i][tx] = W[(size_t)(k0+ty+8*i)*N + n0+tx];
    __syncthreads();
    #pragma unroll
    for (int i = 0; i < 4; i++) {
        int nl = ty + 8*i;
        Bp[(size_t)(n0+nl)*K + k0+tx] = __float2half_rn(ts[tx][nl]);
    }
}

// ---------------- mma.sync fp16 GEMM (hi-only inputs) ----------------
// splitOut: 0 = fp32 C, 2 = fp16 hi only.
// ldc: row stride for C/Cah/add (supports sub-GEMM column slices).
#define GBK 64
#define NSTG 3
#define STB 16384
#define STAGE_BYTES (2*STB)
#define HG_SMEM (NSTG*STAGE_BYTES)

__global__ __launch_bounds__(256, 2) void hgemm_kernel(
    const __half* __restrict__ Ah, const __half* __restrict__ Bp,
    const float* __restrict__ bias, const float* __restrict__ add,
    float* __restrict__ C, __half* __restrict__ Cah,
    int M, int N, int ldc, int K, int act, int splitOut)
{
    extern __shared__ char dsm[];
    const uint32_t sb = smem_u32(dsm);
    const int tid = threadIdx.x;
    const int lane = tid & 31, wid = tid >> 5;
    const int row0 = blockIdx.y * 128, col0 = blockIdx.x * 128;
    const int NT = K / GBK;

    const int wm = (wid >> 2) * 64;
    const int wn = (wid & 3) * 32;

    float acc[4][4][4];
    #pragma unroll
    for (int i=0;i<4;i++)
        #pragma unroll
        for (int j=0;j<4;j++)
            #pragma unroll
            for (int c=0;c<4;c++) acc[i][j][c]=0.f;

    auto load_tile = [&](int t, int s) {
        int k0 = t * GBK;
        uint32_t stA = sb + s*STAGE_BYTES;
        uint32_t stB = stA + STB;
        #pragma unroll
        for (int i = 0; i < 4; i++) {
            int ch = i*256 + tid;
            int r = ch >> 3, c = (ch & 7) * 8;
            cpa16(stA + SWZ(ch*16), Ah + (size_t)(row0 + r)*K + k0 + c);
            cpa16(stB + SWZ(ch*16), Bp + (size_t)(col0 + r)*K + k0 + c);
        }
        asm volatile("cp.async.commit_group;" ::: "memory");
    };

    load_tile(0, 0);
    if (NT > 1) load_tile(1, 1);

    const int aRow = wm + (lane & 15);
    const int aColB = ((lane >> 4) & 1) * 16;
    const int bRow = wn + (lane & 7) + ((lane >> 4) & 1) * 8;
    const int bColB = ((lane >> 3) & 1) * 16;

    for (int t = 0; t < NT; t++) {
        if (t < NT-1) asm volatile("cp.async.wait_group 1;" ::: "memory");
        else          asm volatile("cp.async.wait_group 0;" ::: "memory");
        __syncthreads();
        if (t + 2 < NT) load_tile(t + 2, (t + 2) % NSTG);
        uint32_t stA = sb + (t % NSTG)*STAGE_BYTES;
        uint32_t stB = stA + STB;
        #pragma unroll
        for (int kk = 0; kk < 4; kk++) {
            uint32_t af[4][4];
            #pragma unroll
            for (int mt = 0; mt < 4; mt++) {
                uint32_t addr = stA + SWZ((uint32_t)(aRow + mt*16)*128 + kk*32 + aColB);
                LDSM4(af[mt][0], af[mt][1], af[mt][2], af[mt][3], addr);
            }
            uint32_t bf[4][2];
            #pragma unroll
            for (int nt2 = 0; nt2 < 2; nt2++) {
                uint32_t r0,r1,r2,r3;
                uint32_t addr = stB + SWZ((uint32_t)(bRow + nt2*16)*128 + kk*32 + bColB);
                LDSM4(r0, r1, r2, r3, addr);
                bf[nt2*2][0]=r0; bf[nt2*2][1]=r1; bf[nt2*2+1][0]=r2; bf[nt2*2+1][1]=r3;
            }
            #pragma unroll
            for (int mt = 0; mt < 4; mt++)
                #pragma unroll
                for (int nt = 0; nt < 4; nt++)
                    MMA16816(acc[mt][nt], af[mt], bf[nt]);
        }
        __syncthreads();
    }

    const int erow = lane >> 2, ecol = (lane & 3) * 2;
    #pragma unroll
    for (int mt = 0; mt < 4; mt++) {
        #pragma unroll
        for (int half_ = 0; half_ < 2; half_++) {
            int row = row0 + wm + mt*16 + erow + half_*8;
            size_t rbase = (size_t)row * ldc;
            #pragma unroll
            for (int nt = 0; nt < 4; nt++) {
                int col = col0 + wn + nt*8 + ecol;
                float v0 = acc[mt][nt][half_*2+0];
                float v1 = acc[mt][nt][half_*2+1];
                if (bias) { v0 += bias[col]; v1 += bias[col+1]; }
                if (act)  { v0 = gelu_f(v0); v1 = gelu_f(v1); }
                if (add)  {
                    const float2 a2 = *(const float2*)&add[rbase + col];
                    v0 += a2.x; v1 += a2.y;
                }
                if (splitOut) {
                    *(__half2*)&Cah[rbase + col] =
                        __halves2half2(__float2half_rn(v0), __float2half_rn(v1));
                } else {
                    *(float2*)&C[rbase + col] = make_float2(v0, v1);
                }
            }
        }
    }
}

// ---------------- Per-segment memory contributions (stride QS) ----------------
__global__ void segkv_kernel(const float* __restrict__ k, const float* __restrict__ v,
                             float* __restrict__ ms, float* __restrict__ zs)
{
    __shared__ float sks[32][128];
    __shared__ float svs[32][128];
    __shared__ float zacc[128];
    const int seg = blockIdx.x, bh = blockIdx.y;
    const int b = bh >> 3, h = bh & 7;
    const int tid = threadIdx.x;
    const int ty = tid >> 4, tx = tid & 15;
    float acc[8][8];
    #pragma unroll
    for (int i=0;i<8;i++)
        #pragma unroll
        for (int j=0;j<8;j++) acc[i][j]=0.f;
    if (tid < 128) zacc[tid] = 0.f;
    size_t base = ((size_t)b*SS + seg*SEG_)*QS + h*DK_;
    for (int p0 = 0; p0 < SEG_; p0 += 32) {
        __syncthreads();
        for (int i = tid; i < 32*32; i += 256) {
            int row = i >> 5, c4 = (i & 31)*4;
            float4 kv = *(const float4*)&k[base + (size_t)(p0+row)*QS + c4];
            kv.x = kv.x>0.f?kv.x+1.f:__expf(kv.x);
            kv.y = kv.y>0.f?kv.y+1.f:__expf(kv.y);
            kv.z = kv.z>0.f?kv.z+1.f:__expf(kv.z);
            kv.w = kv.w>0.f?kv.w+1.f:__expf(kv.w);
            *(float4*)&sks[row][c4] = kv;
            *(float4*)&svs[row][c4] = *(const float4*)&v[base + (size_t)(p0+row)*QS + c4];
        }
        __syncthreads();
        if (tid < 128) {
            float za = 0.f;
            for (int p = 0; p < 32; p++) za += sks[p][tid];
            zacc[tid] += za;
        }
        #pragma unroll 4
        for (int p = 0; p < 32; p++) {
            float4 k0 = *(const float4*)&sks[p][ty*8];
            float4 k1 = *(const float4*)&sks[p][ty*8+4];
            float4 v0 = *(const float4*)&svs[p][tx*8];
            float4 v1 = *(const float4*)&svs[p][tx*8+4];
            float kr[8] = {k0.x,k0.y,k0.z,k0.w,k1.x,k1.y,k1.z,k1.w};
            float vr[8] = {v0.x,v0.y,v0.z,v0.w,v1.x,v1.y,v1.z,v1.w};
            #pragma unroll
            for (int i=0;i<8;i++)
                #pragma unroll
                for (int j=0;j<8;j++) acc[i][j] += kr[i]*vr[j];
        }
    }
    size_t obase = ((size_t)seg*32 + bh)*DK_*DK_;
    #pragma unroll
    for (int i=0;i<8;i++)
        #pragma unroll
        for (int j=0;j<8;j++)
            ms[obase + (size_t)(ty*8+i)*DK_ + tx*8+j] = acc[i][j];
    if (tid < 128) zs[((size_t)seg*32 + bh)*DK_ + tid] = zacc[tid];
}

// ---------------- Exclusive prefix over 8 segments ----------------
__global__ void prefix_kernel(const float* __restrict__ ms, const float* __restrict__ zs,
                              float* __restrict__ mp, float* __restrict__ zp)
{
    size_t idx = (size_t)blockIdx.x*256 + threadIdx.x;
    const size_t stride = (size_t)BB*HH*DK_*DK_;
    if (idx < stride) {
        float a = 0.f;
        #pragma unroll
        for (int t = 0; t < NSEG; t++) { mp[t*stride + idx] = a; a += ms[t*stride + idx]; }
    }
    if (idx < (size_t)BB*HH*DK_) {
        const size_t zstr = (size_t)BB*HH*DK_;
        float a = 1.f/128.f;
        #pragma unroll
        for (int t = 0; t < NSEG; t++) { zp[t*zstr + idx] = a; a += zs[t*zstr + idx]; }
    }
}

// ---------------- Attention: register-blocked + shuffle softmax ----------------
#define AP 132
#define SPP 68
#define ATTN_SMEM_FLOATS (64*AP*2 + 64*128 + 64*SPP + 128 + 3*64)
__global__ __launch_bounds__(256, 1) void attn_kernel(
    const float* __restrict__ q, const float* __restrict__ k,
    const float* __restrict__ v, const float* __restrict__ memp,
    const float* __restrict__ zp, const float* __restrict__ betas,
    __half* __restrict__ Oah)
{
    extern __shared__ float sh[];
    float* Qs  = sh;                 // [64][AP]
    float* Ks  = Qs + 64*AP;         // [64][AP]  (later reused for sq)
    float* Vs  = Ks + 64*AP;         // [64][128] (later reused for M chunks)
    float* Spt = Vs + 64*128;        // [64 c][SPP]
    float* Zs  = Spt + 64*SPP;       // [128]
    float* mrow = Zs + 128;
    float* lrow = mrow + 64;
    float* drow = lrow + 64;

    const int qt = blockIdx.x, seg = blockIdx.y;
    const int b = blockIdx.z >> 3, h = blockIdx.z & 7;
    const int tid = threadIdx.x;
    const int ty = tid >> 4, tx = tid & 15;

    const float* Z = zp + (((size_t)seg*BB + b)*HH + h)*DK_;
    size_t qbase = ((size_t)b*SS + seg*SEG_ + qt*64)*QS + h*DK_;
    #pragma unroll
    for (int i = tid; i < 64*32; i += 256) {
        int row = i >> 5, c4 = (i & 31)*4;
        *(float4*)&Qs[row*AP + c4] = *(const float4*)&q[qbase + (size_t)row*QS + c4];
    }
    if (tid < 128) Zs[tid] = Z[tid];
    if (tid < 64) { mrow[tid] = -INFINITY; lrow[tid] = 0.f; }
    float o[4][8];
    #pragma unroll
    for (int i=0;i<4;i++)
        #pragma unroll
        for (int j=0;j<8;j++) o[i][j]=0.f;
    __syncthreads();

    const float scale = 0.08838834764831845f;
    for (int kt = 0; kt <= qt; kt++) {
        size_t kbase = ((size_t)b*SS + seg*SEG_ + kt*64)*QS + h*DK_;
        #pragma unroll
        for (int i = tid; i < 64*32; i += 256) {
            int row = i >> 5, c4 = (i & 31)*4;
            *(float4*)&Ks[row*AP + c4] = *(const float4*)&k[kbase + (size_t)row*QS + c4];
            *(float4*)&Vs[row*128 + c4] = *(const float4*)&v[kbase + (size_t)row*QS + c4];
        }
        __syncthreads();

        // S = Q @ K^T (4x4 per thread)
        float s[4][4];
        #pragma unroll
        for (int i=0;i<4;i++)
            #pragma unroll
            for (int j=0;j<4;j++) s[i][j]=0.f;
        #pragma unroll 4
        for (int d = 0; d < 128; d += 4) {
            float4 qv[4], kv[4];
            #pragma unroll
            for (int i=0;i<4;i++) qv[i] = *(const float4*)&Qs[(ty*4+i)*AP + d];
            #pragma unroll
            for (int j=0;j<4;j++) kv[j] = *(const float4*)&Ks[(tx*4+j)*AP + d];
            #pragma unroll
            for (int i=0;i<4;i++)
                #pragma unroll
                for (int j=0;j<4;j++)
                    s[i][j] += qv[i].x*kv[j].x + qv[i].y*kv[j].y
                             + qv[i].z*kv[j].z + qv[i].w*kv[j].w;
        }
        // scale + causal mask in registers
        #pragma unroll
        for (int i=0;i<4;i++)
            #pragma unroll
            for (int j=0;j<4;j++) {
                float vv = s[i][j]*scale;
                if (kt == qt && (tx*4+j) > (ty*4+i)) vv = -INFINITY;
                s[i][j] = vv;
            }

        // register+shuffle softmax stats (16-lane butterfly across tx)
        float al_[4], ls_[4], mx_[4];
        #pragma unroll
        for (int i=0;i<4;i++) {
            float rm = fmaxf(fmaxf(s[i][0],s[i][1]), fmaxf(s[i][2],s[i][3]));
            #pragma unroll
            for (int off = 1; off < 16; off <<= 1)
                rm = fmaxf(rm, __shfl_xor_sync(0xffffffffu, rm, off));
            float mold = mrow[ty*4+i];
            float mx = fmaxf(mold, rm);
            mx_[i] = mx;
            al_[i] = __expf(mold - mx);
            float ps = 0.f;
            #pragma unroll
            for (int j=0;j<4;j++) {
                float p = __expf(s[i][j] - mx);
                Spt[(tx*4+j)*SPP + ty*4+i] = p;
                ps += p;
            }
            #pragma unroll
            for (int off = 1; off < 16; off <<= 1)
                ps += __shfl_xor_sync(0xffffffffu, ps, off);
            ls_[i] = ps;
        }
        __syncthreads();   // Spt visible; all mrow reads done
        if (tx == 0) {
            #pragma unroll
            for (int i=0;i<4;i++) {
                int r = ty*4 + i;
                mrow[r] = mx_[i];
                lrow[r] = lrow[r]*al_[i] + ls_[i];
            }
        }

        // rescale + PV
        #pragma unroll
        for (int i=0;i<4;i++)
            #pragma unroll
            for (int j=0;j<8;j++) o[i][j] *= al_[i];
        #pragma unroll 2
        for (int c = 0; c < 64; c++) {
            float4 p4 = *(const float4*)&Spt[c*SPP + ty*4];
            float pp[4] = {p4.x, p4.y, p4.z, p4.w};
            float4 v0 = *(const float4*)&Vs[c*128 + tx*8];
            float4 v1 = *(const float4*)&Vs[c*128 + tx*8 + 4];
            float vr[8] = {v0.x,v0.y,v0.z,v0.w,v1.x,v1.y,v1.z,v1.w};
            #pragma unroll
            for (int i=0;i<4;i++)
                #pragma unroll
                for (int j=0;j<8;j++) o[i][j] += pp[i]*vr[j];
        }
        __syncthreads();   // mrow/lrow writes visible; Ks/Vs safe to overwrite
    }

    // ---- retrieval: sq = elu(q)+1 into Ks ----
    #pragma unroll
    for (int i = tid; i < 64*128; i += 256) {
        int row = i >> 7, d = i & 127;
        float qv = Qs[row*AP + d];
        Ks[row*AP + d] = qv > 0.f ? qv + 1.f : __expf(qv);
    }
    __syncthreads();
    if (tid < 64) {
        float ds = 0.f;
        #pragma unroll 4
        for (int d = 0; d < 128; d += 4) {
            float4 sq4 = *(const float4*)&Ks[tid*AP + d];
            float4 z4  = *(const float4*)&Zs[d];
            ds += sq4.x*z4.x + sq4.y*z4.y + sq4.z*z4.z + sq4.w*z4.w;
        }
        drow[tid] = ds;
    }

    const float* M = memp + (((size_t)seg*BB + b)*HH + h)*DK_*DK_;
    float am[4][8];
    #pragma unroll
    for (int i=0;i<4;i++)
        #pragma unroll
        for (int j=0;j<8;j++) am[i][j]=0.f;
    for (int d0 = 0; d0 < 128; d0 += 32) {
        __syncthreads();
        #pragma unroll
        for (int i = tid; i < 32*32; i += 256) {
            int row = i >> 5, c4 = (i & 31)*4;
            *(float4*)&Vs[row*128 + c4] = *(const float4*)&M[(size_t)(d0+row)*128 + c4];
        }
        __syncthreads();
        #pragma unroll 2
        for (int dd = 0; dd < 32; dd += 4) {
            float sqa[4][4];
            #pragma unroll
            for (int i=0;i<4;i++) {
                float4 s4 = *(const float4*)&Ks[(ty*4+i)*AP + d0 + dd];
                sqa[i][0]=s4.x; sqa[i][1]=s4.y; sqa[i][2]=s4.z; sqa[i][3]=s4.w;
            }
            #pragma unroll
            for (int t = 0; t < 4; t++) {
                float4 m0 = *(const float4*)&Vs[(dd+t)*128 + tx*8];
                float4 m1 = *(const float4*)&Vs[(dd+t)*128 + tx*8 + 4];
                float mr[8] = {m0.x,m0.y,m0.z,m0.w,m1.x,m1.y,m1.z,m1.w};
                #pragma unroll
                for (int i=0;i<4;i++)
                    #pragma unroll
                    for (int j=0;j<8;j++) am[i][j] += sqa[i][t]*mr[j];
            }
        }
    }

    // ---- gate + write hi-only fp16 output (row stride DD) ----
    float gte[8];
    #pragma unroll
    for (int j=0;j<8;j++)
        gte[j] = 1.f / (1.f + __expf(-betas[h*DK_ + tx*8 + j]));
    #pragma unroll
    for (int i=0;i<4;i++) {
        int r = ty*4 + i;
        float dinv = 1.f / drow[r];
        float linv = 1.f / lrow[r];
        size_t ob = ((size_t)b*SS + seg*SEG_ + qt*64 + r)*DD + h*DK_ + tx*8;
        #pragma unroll
        for (int j=0;j<8;j+=2) {
            float u0 = gte[j]  *(am[i][j]  *dinv) + (1.f-gte[j])  *(o[i][j]  *linv);
            float u1 = gte[j+1]*(am[i][j+1]*dinv) + (1.f-gte[j+1])*(o[i][j+1]*linv);
            *(__half2*)&Oah[ob + j] = __halves2half2(__float2half_rn(u0), __float2half_rn(u1));
        }
    }
}

// ---------------- launch ----------------
extern "C" void kernel_launch(void* const* d_in, const int* in_sizes, int n_in,
                              void* d_out, int out_size)
{
    const float* x     = (const float*)d_in[0];
    const float* ln_g  = (const float*)d_in[1];
    const float* ln_b  = (const float*)d_in[2];
    const float* Wq    = (const float*)d_in[3];
    const float* Wk    = (const float*)d_in[4];
    const float* Wv    = (const float*)d_in[5];
    const float* Wo    = (const float*)d_in[6];
    const float* betas = (const float*)d_in[7];
    const float* w1    = (const float*)d_in[8];
    const float* b1    = (const float*)d_in[9];
    const float* w2    = (const float*)d_in[10];
    const float* b2    = (const float*)d_in[11];
    float* out = (float*)d_out;

    float *qkv, *x1, *ff, *ms, *mp, *zs, *zp;
    __half *ah, *bqkv, *bo, *bw1, *bw2;
    cudaGetSymbolAddress((void**)&qkv, g_qkv);
    cudaGetSymbolAddress((void**)&x1, g_x1);
    cudaGetSymbolAddress((void**)&ff, g_ff);
    cudaGetSymbolAddress((void**)&ms, g_ms);
    cudaGetSymbolAddress((void**)&mp, g_mp);
    cudaGetSymbolAddress((void**)&zs, g_zs);
    cudaGetSymbolAddress((void**)&zp, g_zp);
    cudaGetSymbolAddress((void**)&ah, g_ah);
    cudaGetSymbolAddress((void**)&bqkv, g_bqkv);
    cudaGetSymbolAddress((void**)&bo, g_bo);
    cudaGetSymbolAddress((void**)&bw1, g_bw1);
    cudaGetSymbolAddress((void**)&bw2, g_bw2);

    __half* ah2 = (__half*)ff;     // FFN1 hi-only output

    const int attn_smem = ATTN_SMEM_FLOATS * 4;
    cudaFuncSetAttribute(attn_kernel, cudaFuncAttributeMaxDynamicSharedMemorySize, attn_smem);
    cudaFuncSetAttribute(hgemm_kernel, cudaFuncAttributeMaxDynamicSharedMemorySize, HG_SMEM);

    dim3 wblk(32, 8);

    // weight prep: fused QKV rows [0:1024)=Wq, [1024:2048)=Wk, [2048:3072)=Wv
    prep_w_kernel<<<dim3(1024/32, 1024/32), wblk>>>(Wq, bqkv,                      1024, 1024);
    prep_w_kernel<<<dim3(1024/32, 1024/32), wblk>>>(Wk, bqkv + (size_t)1024*1024,  1024, 1024);
    prep_w_kernel<<<dim3(1024/32, 1024/32), wblk>>>(Wv, bqkv + (size_t)2048*1024,  1024, 1024);
    prep_w_kernel<<<dim3(1024/32, 1024/32), wblk>>>(Wo, bo, 1024, 1024);
    prep_w_kernel<<<dim3(4096/32, 1024/32), wblk>>>(w1, bw1, 1024, 4096);
    prep_w_kernel<<<dim3(1024/32, 4096/32), wblk>>>(w2, bw2, 4096, 1024);

    // 1) LN1 -> fp16 hi
    ln_kernel<<<MROWS, 256>>>(x, ln_g, ln_b, ah);
    // 2) fused QKV projection (N=3072, hi-only)
    hgemm_kernel<<<dim3(QS/128, MROWS/128), 256, HG_SMEM>>>(ah, bqkv, nullptr, nullptr,
                                                            qkv, nullptr, MROWS, QS, QS, DD, 0, 0);
    // 3-5) infini-attention
    segkv_kernel<<<dim3(NSEG, BB*HH), 256>>>(qkv + 1024, qkv + 2048, ms, zs);
    prefix_kernel<<<(BB*HH*DK_*DK_)/256, 256>>>(ms, zs, mp, zp);
    attn_kernel<<<dim3(8, NSEG, BB*HH), 256, attn_smem>>>(qkv, qkv + 1024, qkv + 2048,
                                                          mp, zp, betas, ah);
    // 6) output projection + residual
    dim3 g1(DD/128, MROWS/128);
    hgemm_kernel<<<g1, 256, HG_SMEM>>>(ah, bo, nullptr, x, x1, nullptr,
                                       MROWS, DD, DD, DD, 0, 0);
    // 7) LN2 -> fp16 hi
    ln_kernel<<<MROWS, 256>>>(x1, ln_g, ln_b, ah);
    // 8) FFN1 + bias + gelu -> fp16 hi
    hgemm_kernel<<<dim3(DH_/128, MROWS/128), 256, HG_SMEM>>>(ah, bw1, b1, nullptr, nullptr,
                                                             ah2, MROWS, DH_, DH_, DD, 1, 2);
    // 9) FFN2 + bias + residual -> out
    hgemm_kernel<<<dim3(DD/128, MROWS/128), 256, HG_SMEM>>>(ah2, bw2, b2, x1, out,
                                                            nullptr, MROWS, DD, DD, DH_, 0, 0);
}